// round 11
// baseline (speedup 1.0000x reference)
#include <cuda_runtime.h>
#include <cuda_bf16.h>
#include <math.h>
#include <stdint.h>

// Shapes fixed: B=32, LV=196, LT=40, D=512, H=8, DH=64, R=B*LV=6272 (=49*128)

// ---------------------------------------------------------------------------
// Scratch buffer layout (float slots)
// ---------------------------------------------------------------------------
#define OFF_SM    0u
#define OFF_B2    16384u
#define OFF_BQ    32768u
#define OFF_W67   33280u
#define OFF_WQ    295424u
#define OFF_S     557568u
#define OFF_RP    558592u
#define OFF_CP    759296u
#define OFF_V1    960000u
#define OFF_QKV   4171264u
#define OFF_AOH   13805056u
#define OFF_AOL   15410688u
#define OFF_AFTH  17016320u
#define OFF_AFTL  18621952u
#define OFF_QLH   20227584u
#define OFF_QLL   21833216u
#define OFF_KLH   23438848u
#define OFF_KLL   25044480u
#define OFF_WQH   26650112u
#define OFF_WQL   26715648u
#define OFF_KWH   26781184u
#define OFF_KWL   26846720u
#define TOTAL_F   26912256u

__device__ __align__(256) float g_buf[TOTAL_F];

// ---------------------------------------------------------------------------
// mma.sync / ldmatrix / cp.async helpers
// ---------------------------------------------------------------------------
__device__ __forceinline__ uint32_t smem_u32(const void* p) {
    uint32_t a;
    asm("{ .reg .u64 t; cvta.to.shared.u64 t, %1; cvt.u32.u64 %0, t; }" : "=r"(a) : "l"(p));
    return a;
}
__device__ __forceinline__ void ldsm_x4(uint32_t* r, uint32_t addr) {
    asm volatile("ldmatrix.sync.aligned.m8n8.x4.shared.b16 {%0,%1,%2,%3}, [%4];"
                 : "=r"(r[0]), "=r"(r[1]), "=r"(r[2]), "=r"(r[3]) : "r"(addr));
}
__device__ __forceinline__ void ldsm_x2(uint32_t* r, uint32_t addr) {
    asm volatile("ldmatrix.sync.aligned.m8n8.x2.shared.b16 {%0,%1}, [%2];"
                 : "=r"(r[0]), "=r"(r[1]) : "r"(addr));
}
__device__ __forceinline__ void mma_bf16(float* d, const uint32_t* a, const uint32_t* b) {
    asm volatile("mma.sync.aligned.m16n8k16.row.col.f32.bf16.bf16.f32 "
                 "{%0,%1,%2,%3}, {%4,%5,%6,%7}, {%8,%9}, {%0,%1,%2,%3};"
                 : "+f"(d[0]), "+f"(d[1]), "+f"(d[2]), "+f"(d[3])
                 : "r"(a[0]), "r"(a[1]), "r"(a[2]), "r"(a[3]), "r"(b[0]), "r"(b[1]));
}
__device__ __forceinline__ void cp_async16(uint32_t dst, const void* src) {
    asm volatile("cp.async.cg.shared.global [%0], [%1], 16;" :: "r"(dst), "l"(src) : "memory");
}
__device__ __forceinline__ void cp_commit() {
    asm volatile("cp.async.commit_group;" ::: "memory");
}
template<int N>
__device__ __forceinline__ void cp_wait() {
    asm volatile("cp.async.wait_group %0;" :: "n"(N) : "memory");
}
#define SWZ128(off) ((off) ^ (((off) >> 3) & 0x70))

__device__ __forceinline__ unsigned enc_f(float f) {
    unsigned u = __float_as_uint(f);
    return u ^ ((((int)u >> 31)) | 0x80000000u);
}
__device__ __forceinline__ float dec_f(unsigned u) {
    unsigned m = (u & 0x80000000u) ? 0x80000000u : 0xFFFFFFFFu;
    return __uint_as_float(u ^ m);
}

// ---------------------------------------------------------------------------
__global__ void sent_mean_kernel(const float* __restrict__ sentf,
                                 const float* __restrict__ masks,
                                 float* __restrict__ sm) {
    int b = blockIdx.x, d = threadIdx.x;
    float s = 0.f;
    #pragma unroll
    for (int t = 0; t < 40; t++)
        s += sentf[(b * 40 + t) * 512 + d] * masks[b * 40 + t];
    sm[b * 512 + d] = s * (1.f / 40.f);
}

__global__ void bias2_kernel(const float* __restrict__ conv1_w,
                             const float* __restrict__ conv1_b,
                             const float* __restrict__ sm,
                             float* __restrict__ b2) {
    int gw = (blockIdx.x * blockDim.x + threadIdx.x) >> 5;
    int lane = threadIdx.x & 31;
    int b = gw >> 9, o = gw & 511;
    const float* wrow = conv1_w + o * 1024 + 512;
    const float* srow = sm + b * 512;
    float s = 0.f;
    for (int c = lane; c < 512; c += 32) s += wrow[c] * srow[c];
    #pragma unroll
    for (int off = 16; off; off >>= 1) s += __shfl_xor_sync(0xffffffffu, s, off);
    if (lane == 0) b2[b * 512 + o] = conv1_b[o] + s;
}

// warp-per-output: bq[q] = q_b[q] + sum_o q_w[q,o]*conv2_b[o]
__global__ void bq_kernel(const float* __restrict__ q_w,
                          const float* __restrict__ conv2_b,
                          const float* __restrict__ q_b,
                          float* __restrict__ bq) {
    int gw = blockIdx.x * 8 + (threadIdx.x >> 5);
    int lane = threadIdx.x & 31;
    const float* row = q_w + gw * 512;
    float s = 0.f;
    for (int c = lane; c < 512; c += 32) s += row[c] * conv2_b[c];
    #pragma unroll
    for (int off = 16; off; off >>= 1) s += __shfl_xor_sync(0xffffffffu, s, off);
    if (lane == 0) bq[gw] = q_b[gw] + s;
}

// ---------------------------------------------------------------------------
// Small fp32 GEMM for 512x512x512 weight fusions. C = A*B (both row-major).
// ---------------------------------------------------------------------------
__global__ void gemm64_nt(const float* __restrict__ A, const float* __restrict__ B,
                          float* __restrict__ C, int K, int lda, int ldb, int ldc) {
    __shared__ float As[32][65];
    __shared__ float Bs[32][65];
    int tid = threadIdx.x;
    int tx = tid & 15, ty = tid >> 4;
    int n0 = blockIdx.x * 64, m0 = blockIdx.y * 64;
    float acc[4][4] = {};
    for (int k0 = 0; k0 < K; k0 += 32) {
        #pragma unroll
        for (int i = 0; i < 8; i++) {
            int idx = tid + i * 256;
            int k = idx & 31, r = idx >> 5;
            As[k][r] = A[(m0 + r) * lda + k0 + k];
            int n = idx & 63, kk = idx >> 6;
            Bs[kk][n] = B[(k0 + kk) * ldb + n0 + n];
        }
        __syncthreads();
        #pragma unroll
        for (int k = 0; k < 32; k++) {
            float ar[4], br[4];
            #pragma unroll
            for (int i = 0; i < 4; i++) ar[i] = As[k][ty * 4 + i];
            #pragma unroll
            for (int j = 0; j < 4; j++) br[j] = Bs[k][tx * 4 + j];
            #pragma unroll
            for (int i = 0; i < 4; i++)
                #pragma unroll
                for (int j = 0; j < 4; j++) acc[i][j] += ar[i] * br[j];
        }
        __syncthreads();
    }
    #pragma unroll
    for (int i = 0; i < 4; i++)
        #pragma unroll
        for (int j = 0; j < 4; j++)
            C[(m0 + ty * 4 + i) * ldc + n0 + tx * 4 + j] = acc[i][j];
}

// ---------------------------------------------------------------------------
// fp32 SIMT GEMM: C = A(MxK) * B(NxK)^T, 128x128 tile, 8x8 micro, BK=16, dbuf.
// Per-element FMA chain is k-ascending (identical to BK=8 version -> bit-
// identical outputs). MODE 0: plain. MODE 2: +bias[(r/196)*512+n].
// ---------------------------------------------------------------------------
template<int MODE>
__global__ void __launch_bounds__(256) gemm128(
        const float* __restrict__ A, const float* __restrict__ B,
        float* __restrict__ C, const float* __restrict__ bias,
        int K, int lda, int ldb, int ldc) {
    __shared__ float As[2][16][132];
    __shared__ float Bs[2][16][132];
    int tid = threadIdx.x;
    int tx = tid & 15, ty = tid >> 4;
    int row = tid >> 1, seg = tid & 1;
    int m0 = blockIdx.y * 128, n0 = blockIdx.x * 128;

    const float* Abase = A + (m0 + row) * lda + seg * 8;
    const float* Bbase = B + (n0 + row) * ldb + seg * 8;

    float acc[8][8] = {};
    float4 pa0 = *(const float4*)Abase;
    float4 pa1 = *(const float4*)(Abase + 4);
    float4 pb0 = *(const float4*)Bbase;
    float4 pb1 = *(const float4*)(Bbase + 4);
    As[0][seg * 8 + 0][row] = pa0.x; As[0][seg * 8 + 1][row] = pa0.y;
    As[0][seg * 8 + 2][row] = pa0.z; As[0][seg * 8 + 3][row] = pa0.w;
    As[0][seg * 8 + 4][row] = pa1.x; As[0][seg * 8 + 5][row] = pa1.y;
    As[0][seg * 8 + 6][row] = pa1.z; As[0][seg * 8 + 7][row] = pa1.w;
    Bs[0][seg * 8 + 0][row] = pb0.x; Bs[0][seg * 8 + 1][row] = pb0.y;
    Bs[0][seg * 8 + 2][row] = pb0.z; Bs[0][seg * 8 + 3][row] = pb0.w;
    Bs[0][seg * 8 + 4][row] = pb1.x; Bs[0][seg * 8 + 5][row] = pb1.y;
    Bs[0][seg * 8 + 6][row] = pb1.z; Bs[0][seg * 8 + 7][row] = pb1.w;
    __syncthreads();

    int NK = K >> 4;
    for (int kt = 0; kt < NK; kt++) {
        int cur = kt & 1;
        if (kt + 1 < NK) {
            pa0 = *(const float4*)(Abase + (kt + 1) * 16);
            pa1 = *(const float4*)(Abase + (kt + 1) * 16 + 4);
            pb0 = *(const float4*)(Bbase + (kt + 1) * 16);
            pb1 = *(const float4*)(Bbase + (kt + 1) * 16 + 4);
        }
        #pragma unroll
        for (int k = 0; k < 16; k++) {
            float ar[8], br[8];
            *(float4*)(ar)     = *(const float4*)&As[cur][k][ty * 4];
            *(float4*)(ar + 4) = *(const float4*)&As[cur][k][64 + ty * 4];
            *(float4*)(br)     = *(const float4*)&Bs[cur][k][tx * 4];
            *(float4*)(br + 4) = *(const float4*)&Bs[cur][k][64 + tx * 4];
            #pragma unroll
            for (int i = 0; i < 8; i++)
                #pragma unroll
                for (int j = 0; j < 8; j++)
                    acc[i][j] += ar[i] * br[j];
        }
        if (kt + 1 < NK) {
            int nxt = cur ^ 1;
            As[nxt][seg * 8 + 0][row] = pa0.x; As[nxt][seg * 8 + 1][row] = pa0.y;
            As[nxt][seg * 8 + 2][row] = pa0.z; As[nxt][seg * 8 + 3][row] = pa0.w;
            As[nxt][seg * 8 + 4][row] = pa1.x; As[nxt][seg * 8 + 5][row] = pa1.y;
            As[nxt][seg * 8 + 6][row] = pa1.z; As[nxt][seg * 8 + 7][row] = pa1.w;
            Bs[nxt][seg * 8 + 0][row] = pb0.x; Bs[nxt][seg * 8 + 1][row] = pb0.y;
            Bs[nxt][seg * 8 + 2][row] = pb0.z; Bs[nxt][seg * 8 + 3][row] = pb0.w;
            Bs[nxt][seg * 8 + 4][row] = pb1.x; Bs[nxt][seg * 8 + 5][row] = pb1.y;
            Bs[nxt][seg * 8 + 6][row] = pb1.z; Bs[nxt][seg * 8 + 7][row] = pb1.w;
        }
        __syncthreads();
    }

    #pragma unroll
    for (int i = 0; i < 8; i++) {
        int r = m0 + ty * 4 + (i & 3) + ((i >> 2) << 6);
        int boff = (MODE == 2) ? (r / 196) * 512 : 0;
        #pragma unroll
        for (int hj = 0; hj < 2; hj++) {
            int c = n0 + tx * 4 + (hj << 6);
            float4 v;
            v.x = acc[i][hj * 4 + 0]; v.y = acc[i][hj * 4 + 1];
            v.z = acc[i][hj * 4 + 2]; v.w = acc[i][hj * 4 + 3];
            if (MODE == 2) {
                v.x += bias[boff + c]; v.y += bias[boff + c + 1];
                v.z += bias[boff + c + 2]; v.w += bias[boff + c + 3];
            }
            *(float4*)&C[r * ldc + c] = v;
        }
    }
}

// ---------------------------------------------------------------------------
// Vectorized split: hi = bf16(x), lo = bf16(x - hi). Contiguous, n % 4 == 0.
// ---------------------------------------------------------------------------
__global__ void split_vec_kernel(const float4* __restrict__ src,
                                 uint2* __restrict__ hi,
                                 uint2* __restrict__ lo, int n4) {
    for (int i = blockIdx.x * blockDim.x + threadIdx.x; i < n4; i += gridDim.x * blockDim.x) {
        float4 x = src[i];
        __nv_bfloat162 h0, h1, l0, l1;
        h0.x = __float2bfloat16(x.x); h0.y = __float2bfloat16(x.y);
        h1.x = __float2bfloat16(x.z); h1.y = __float2bfloat16(x.w);
        l0.x = __float2bfloat16(x.x - __bfloat162float(h0.x));
        l0.y = __float2bfloat16(x.y - __bfloat162float(h0.y));
        l1.x = __float2bfloat16(x.z - __bfloat162float(h1.x));
        l1.y = __float2bfloat16(x.w - __bfloat162float(h1.y));
        hi[i] = make_uint2(*(uint32_t*)&h0, *(uint32_t*)&h1);
        lo[i] = make_uint2(*(uint32_t*)&l0, *(uint32_t*)&l1);
    }
}

__global__ void init_parts_kernel(unsigned* __restrict__ p, int n) {
    for (int i = blockIdx.x * blockDim.x + threadIdx.x; i < n; i += gridDim.x * blockDim.x)
        p[i] = 0x007FFFFFu;   // enc(-inf)
}

// ---------------------------------------------------------------------------
// bf16x3 mma GEMM (MODE 1): C[M,N] = A(Mx512)@W(Nx512)^T + bias[n],
// output as bf16 hi/lo splits. 128x128 CTA tile, 8 warps x (64x32).
// ---------------------------------------------------------------------------
#define MG_SMEM 65536
#define SM_AH 0
#define SM_AL 16384
#define SM_BH 32768
#define SM_BL 49152

__global__ void __launch_bounds__(256) mma_gemm_b1(
        const __nv_bfloat16* __restrict__ Ah, const __nv_bfloat16* __restrict__ Al,
        const __nv_bfloat16* __restrict__ Wh, const __nv_bfloat16* __restrict__ Wl,
        __nv_bfloat16* __restrict__ outh, __nv_bfloat16* __restrict__ outl,
        const float* __restrict__ bias) {
    extern __shared__ char smem[];
    int tid = threadIdx.x;
    int wid = tid >> 5, lane = tid & 31;
    int m0 = blockIdx.y * 128, n0 = blockIdx.x * 128;
    int wm0 = (wid >> 2) * 64, wn0 = (wid & 3) * 32;

    int a_row = wm0 + (lane & 15);
    int a_ch  = (lane >> 4);
    int b_row = wn0 + (lane & 7);
    int b_ch  = ((lane >> 3) & 1);
    uint32_t smem_b = smem_u32(smem);

    float d[4][4][4];
    #pragma unroll
    for (int i = 0; i < 4; i++)
        #pragma unroll
        for (int j = 0; j < 4; j++)
            #pragma unroll
            for (int q = 0; q < 4; q++) d[i][j][q] = 0.f;

    for (int kc = 0; kc < 8; kc++) {
        __syncthreads();
        #pragma unroll
        for (int t = 0; t < 4; t++) {
            int s2 = tid + t * 256;
            int row = s2 >> 3, sc = s2 & 7;
            uint32_t sw = SWZ128((uint32_t)(row * 128 + sc * 16));
            long ga = (long)(m0 + row) * 512 + kc * 64 + sc * 8;
            long gb = (long)(n0 + row) * 512 + kc * 64 + sc * 8;
            *(uint4*)(smem + SM_AH + sw) = *(const uint4*)(Ah + ga);
            *(uint4*)(smem + SM_AL + sw) = *(const uint4*)(Al + ga);
            *(uint4*)(smem + SM_BH + sw) = *(const uint4*)(Wh + gb);
            *(uint4*)(smem + SM_BL + sw) = *(const uint4*)(Wl + gb);
        }
        __syncthreads();

        #pragma unroll
        for (int ks = 0; ks < 4; ks++) {
            int ach = (ks * 2 + a_ch) ^ (a_row & 7);
            int bch = (ks * 2 + b_ch) ^ (b_row & 7);
            uint32_t ah[4][4], bh[4][2], bl[4][2], al[4][4];
            #pragma unroll
            for (int i = 0; i < 4; i++)
                ldsm_x4(ah[i], smem_b + SM_AH + (a_row + i * 16) * 128 + ach * 16);
            #pragma unroll
            for (int j = 0; j < 4; j++)
                ldsm_x2(bh[j], smem_b + SM_BH + (b_row + j * 8) * 128 + bch * 16);
            #pragma unroll
            for (int i = 0; i < 4; i++)
                #pragma unroll
                for (int j = 0; j < 4; j++) mma_bf16(d[i][j], ah[i], bh[j]);
            #pragma unroll
            for (int j = 0; j < 4; j++)
                ldsm_x2(bl[j], smem_b + SM_BL + (b_row + j * 8) * 128 + bch * 16);
            #pragma unroll
            for (int i = 0; i < 4; i++)
                #pragma unroll
                for (int j = 0; j < 4; j++) mma_bf16(d[i][j], ah[i], bl[j]);
            #pragma unroll
            for (int i = 0; i < 4; i++)
                ldsm_x4(al[i], smem_b + SM_AL + (a_row + i * 16) * 128 + ach * 16);
            #pragma unroll
            for (int i = 0; i < 4; i++)
                #pragma unroll
                for (int j = 0; j < 4; j++) mma_bf16(d[i][j], al[i], bh[j]);
        }
    }

    int fr = lane >> 2, fc = (lane & 3) * 2;
    #pragma unroll
    for (int i = 0; i < 4; i++) {
        #pragma unroll
        for (int j = 0; j < 4; j++) {
            int gc = n0 + wn0 + j * 8 + fc;
            float b0 = bias[gc], b1 = bias[gc + 1];
            #pragma unroll
            for (int hh = 0; hh < 2; hh++) {
                int gr = m0 + wm0 + i * 16 + fr + hh * 8;
                float v0 = d[i][j][hh * 2 + 0] + b0;
                float v1 = d[i][j][hh * 2 + 1] + b1;
                __nv_bfloat162 hp, lp;
                hp.x = __float2bfloat16(v0);
                hp.y = __float2bfloat16(v1);
                lp.x = __float2bfloat16(v0 - __bfloat162float(hp.x));
                lp.y = __float2bfloat16(v1 - __bfloat162float(hp.y));
                *(uint32_t*)&outh[(long)gr * 512 + gc] = *(uint32_t*)&hp;
                *(uint32_t*)&outl[(long)gr * 512 + gc] = *(uint32_t*)&lp;
            }
        }
    }
}

// ---------------------------------------------------------------------------
// Attention: one CTA per (b,h). 4 query rows per warp iteration, d-outer QK.
// (unchanged from round 10)
// ---------------------------------------------------------------------------
__global__ void attn_kernel(const float* __restrict__ qkv,
                            __nv_bfloat16* __restrict__ outh,
                            __nv_bfloat16* __restrict__ outl) {
    int b = blockIdx.x >> 3, h = blockIdx.x & 7;
    extern __shared__ float smemf[];
    float* ks = smemf;                    // 196*65
    float* vs = smemf + 196 * 65;         // 196*65
    float* qs = smemf + 2 * 196 * 65;     // 8*256
    int tid = threadIdx.x;
    const float* base = qkv + b * (196 * 1536) + h * 64;
    for (int idx = tid; idx < 196 * 64; idx += 256) {
        int m = idx >> 6, d = idx & 63;
        ks[m * 65 + d] = base[m * 1536 + 512 + d];
        vs[m * 65 + d] = base[m * 1536 + 1024 + d];
    }
    __syncthreads();
    int w = tid >> 5, lane = tid & 31;
    float* q0 = qs + w * 256;

    for (int l0 = w; l0 < 196; l0 += 32) {
        bool has[4];
        #pragma unroll
        for (int rr = 0; rr < 4; rr++) {
            int lr = l0 + rr * 8;
            has[rr] = lr < 196;
            if (has[rr]) {
                q0[rr * 64 + lane]      = base[lr * 1536 + lane];
                q0[rr * 64 + lane + 32] = base[lr * 1536 + lane + 32];
            } else {
                q0[rr * 64 + lane]      = 0.f;
                q0[rr * 64 + lane + 32] = 0.f;
            }
        }
        __syncwarp();

        float s[4][7];
        #pragma unroll
        for (int rr = 0; rr < 4; rr++)
            #pragma unroll
            for (int j = 0; j < 7; j++) s[rr][j] = 0.f;

        for (int d = 0; d < 64; d++) {
            float kv[7];
            #pragma unroll
            for (int j = 0; j < 6; j++) kv[j] = ks[(j * 32 + lane) * 65 + d];
            kv[6] = (lane < 4) ? ks[(192 + lane) * 65 + d] : 0.f;
            #pragma unroll
            for (int rr = 0; rr < 4; rr++) {
                float qv = q0[rr * 64 + d];
                #pragma unroll
                for (int j = 0; j < 7; j++) s[rr][j] += qv * kv[j];
            }
        }
        #pragma unroll
        for (int rr = 0; rr < 4; rr++) {
            #pragma unroll
            for (int j = 0; j < 7; j++) s[rr][j] *= 0.125f;
            if (lane >= 4) s[rr][6] = -INFINITY;
        }

        float inv[4];
        #pragma unroll
        for (int rr = 0; rr < 4; rr++) {
            float mx = s[rr][0];
            #pragma unroll
            for (int j = 1; j < 7; j++) mx = fmaxf(mx, s[rr][j]);
            #pragma unroll
            for (int off = 16; off; off >>= 1)
                mx = fmaxf(mx, __shfl_xor_sync(0xffffffffu, mx, off));
            float sum = 0.f;
            #pragma unroll
            for (int j = 0; j < 7; j++) { s[rr][j] = expf(s[rr][j] - mx); sum += s[rr][j]; }
            #pragma unroll
            for (int off = 16; off; off >>= 1)
                sum += __shfl_xor_sync(0xffffffffu, sum, off);
            inv[rr] = 1.f / sum;
        }

        float o0[4] = {0.f, 0.f, 0.f, 0.f};
        float o1[4] = {0.f, 0.f, 0.f, 0.f};
        #pragma unroll
        for (int j = 0; j < 7; j++) {
            #pragma unroll
            for (int mm = 0; mm < 32; mm++) {
                int m = j * 32 + mm;
                if (m >= 196) break;
                float v0 = vs[m * 65 + lane];
                float v1 = vs[m * 65 + lane + 32];
                #pragma unroll
                for (int rr = 0; rr < 4; rr++) {
                    float p = __shfl_sync(0xffffffffu, s[rr][j], mm);
                    o0[rr] += p * v0;
                    o1[rr] += p * v1;
                }
            }
        }
        #pragma unroll
        for (int rr = 0; rr < 4; rr++) {
            if (!has[rr]) continue;
            int r = b * 196 + l0 + rr * 8;
            float x0 = o0[rr] * inv[rr], x1 = o1[rr] * inv[rr];
            long i0 = (long)r * 512 + h * 64 + lane;
            __nv_bfloat16 h0 = __float2bfloat16(x0);
            __nv_bfloat16 h1 = __float2bfloat16(x1);
            outh[i0]      = h0;
            outh[i0 + 32] = h1;
            outl[i0]      = __float2bfloat16(x0 - __bfloat162float(h0));
            outl[i0 + 32] = __float2bfloat16(x1 - __bfloat162float(h1));
        }
        __syncwarp();
    }
}

// ---------------------------------------------------------------------------
// Pair kernel via mma.sync bf16x3 with fused row/col max epilogue.
// 2-stage cp.async pipeline (2 x 64KB smem buffers).
// ---------------------------------------------------------------------------
#define PK_SMEM 131072
#define PK_BUF  65536

__global__ void __launch_bounds__(256) pair_mma_kernel(
        const __nv_bfloat16* __restrict__ QLh, const __nv_bfloat16* __restrict__ QLl,
        const __nv_bfloat16* __restrict__ KLh, const __nv_bfloat16* __restrict__ KLl,
        unsigned* __restrict__ rowparts, unsigned* __restrict__ colparts) {
    extern __shared__ char smem[];
    float (*Ct)[130] = (float(*)[130])smem;
    int tid = threadIdx.x;
    int wid = tid >> 5, lane = tid & 31;
    int m0 = blockIdx.y * 128, n0 = blockIdx.x * 128;
    int wm0 = (wid >> 2) * 64, wn0 = (wid & 3) * 32;

    int a_row = wm0 + (lane & 15);
    int a_ch  = (lane >> 4);
    int b_row = wn0 + (lane & 7);
    int b_ch  = ((lane >> 3) & 1);
    uint32_t smem_b = smem_u32(smem);

    float d[4][4][4];
    #pragma unroll
    for (int i = 0; i < 4; i++)
        #pragma unroll
        for (int j = 0; j < 4; j++)
            #pragma unroll
            for (int q = 0; q < 4; q++) d[i][j][q] = 0.f;

    auto stage = [&](int kc, int buf) {
        uint32_t b0 = smem_b + buf * PK_BUF;
        #pragma unroll
        for (int t = 0; t < 4; t++) {
            int s2 = tid + t * 256;
            int row = s2 >> 3, sc = s2 & 7;
            uint32_t sw = SWZ128((uint32_t)(row * 128 + sc * 16));
            long ga = (long)(m0 + row) * 512 + kc * 64 + sc * 8;
            long gb = (long)(n0 + row) * 512 + kc * 64 + sc * 8;
            cp_async16(b0 + SM_AH + sw, QLh + ga);
            cp_async16(b0 + SM_AL + sw, QLl + ga);
            cp_async16(b0 + SM_BH + sw, KLh + gb);
            cp_async16(b0 + SM_BL + sw, KLl + gb);
        }
        cp_commit();
    };

    stage(0, 0);
    for (int kc = 0; kc < 8; kc++) {
        if (kc < 7) stage(kc + 1, (kc + 1) & 1);
        if (kc < 7) cp_wait<1>(); else cp_wait<0>();
        __syncthreads();
        uint32_t bofs = (uint32_t)((kc & 1) * PK_BUF);

        #pragma unroll
        for (int ks = 0; ks < 4; ks++) {
            int ach = (ks * 2 + a_ch) ^ (a_row & 7);
            int bch = (ks * 2 + b_ch) ^ (b_row & 7);
            uint32_t ah[4][4], bh[4][2], bl[4][2], al[4][4];
            #pragma unroll
            for (int i = 0; i < 4; i++)
                ldsm_x4(ah[i], smem_b + bofs + SM_AH + (a_row + i * 16) * 128 + ach * 16);
            #pragma unroll
            for (int j = 0; j < 4; j++)
                ldsm_x2(bh[j], smem_b + bofs + SM_BH + (b_row + j * 8) * 128 + bch * 16);
            #pragma unroll
            for (int i = 0; i < 4; i++)
                #pragma unroll
                for (int j = 0; j < 4; j++) mma_bf16(d[i][j], ah[i], bh[j]);
            #pragma unroll
            for (int j = 0; j < 4; j++)
                ldsm_x2(bl[j], smem_b + bofs + SM_BL + (b_row + j * 8) * 128 + bch * 16);
            #pragma unroll
            for (int i = 0; i < 4; i++)
                #pragma unroll
                for (int j = 0; j < 4; j++) mma_bf16(d[i][j], ah[i], bl[j]);
            #pragma unroll
            for (int i = 0; i < 4; i++)
                ldsm_x4(al[i], smem_b + bofs + SM_AL + (a_row + i * 16) * 128 + ach * 16);
            #pragma unroll
            for (int i = 0; i < 4; i++)
                #pragma unroll
                for (int j = 0; j < 4; j++) mma_bf16(d[i][j], al[i], bh[j]);
        }
        __syncthreads();
    }

    int fr = lane >> 2, fc = (lane & 3) * 2;
    #pragma unroll
    for (int i = 0; i < 4; i++) {
        #pragma unroll
        for (int j = 0; j < 4; j++) {
            int r = wm0 + i * 16 + fr, c = wn0 + j * 8 + fc;
            *(float2*)&Ct[r][c]     = make_float2(d[i][j][0], d[i][j][1]);
            *(float2*)&Ct[r + 8][c] = make_float2(d[i][j][2], d[i][j][3]);
        }
    }
    __syncthreads();

    if (tid < 128) {
        int r = tid, gr = m0 + r;
        int b0 = n0 / 196;
        int bnd = (b0 + 1) * 196 - n0;
        if (bnd > 128) bnd = 128;
        float m1 = -INFINITY, m2 = -INFINITY;
        for (int c = 0; c < 128; c++) {
            float v = Ct[r][c];
            if (c < bnd) m1 = fmaxf(m1, v); else m2 = fmaxf(m2, v);
        }
        atomicMax(&rowparts[b0 * 6272 + gr], enc_f(m1));
        if (bnd < 128)
            atomicMax(&rowparts[(b0 + 1) * 6272 + gr], enc_f(m2));
    } else {
        int c = tid - 128, gc = n0 + c;
        int a0 = m0 / 196;
        int bnd = (a0 + 1) * 196 - m0;
        if (bnd > 128) bnd = 128;
        float m1 = -INFINITY, m2 = -INFINITY;
        for (int r = 0; r < 128; r++) {
            float v = Ct[r][c];
            if (r < bnd) m1 = fmaxf(m1, v); else m2 = fmaxf(m2, v);
        }
        atomicMax(&colparts[a0 * 6272 + gc], enc_f(m1));
        if (bnd < 128)
            atomicMax(&colparts[(a0 + 1) * 6272 + gc], enc_f(m2));
    }
}

// ---------------------------------------------------------------------------
__global__ void reduce_s_kernel(const unsigned* __restrict__ rowparts,
                                const unsigned* __restrict__ colparts,
                                const float* __restrict__ logit_scale,
                                float* __restrict__ S) {
    int pair = blockIdx.x, tid = threadIdx.x;
    int a = pair >> 5, b = pair & 31;
    float s = 0.f;
    for (int l = tid; l < 196; l += 256)
        s += dec_f(rowparts[b * 6272 + a * 196 + l]);
    for (int m = tid; m < 196; m += 256)
        s += dec_f(colparts[a * 6272 + b * 196 + m]);
    __shared__ float red[256];
    red[tid] = s;
    __syncthreads();
    for (int st = 128; st; st >>= 1) {
        if (tid < st) red[tid] += red[tid + st];
        __syncthreads();
    }
    if (tid == 0) S[pair] = 0.5f * red[0] * (1.f / 196.f) * expf(logit_scale[0]);
}

__global__ void loss_kernel(const float* __restrict__ S, float* __restrict__ out) {
    int tid = threadIdx.x;
    int w = tid >> 5, lane = tid & 31;
    float rv = S[w * 32 + lane];
    float cv = S[lane * 32 + w];
    float rm = rv, cm = cv;
    #pragma unroll
    for (int off = 16; off; off >>= 1) {
        rm = fmaxf(rm, __shfl_xor_sync(0xffffffffu, rm, off));
        cm = fmaxf(cm, __shfl_xor_sync(0xffffffffu, cm, off));
    }
    float re = expf(rv - rm), cex = expf(cv - cm);
    #pragma unroll
    for (int off = 16; off; off >>= 1) {
        re  += __shfl_xor_sync(0xffffffffu, re, off);
        cex += __shfl_xor_sync(0xffffffffu, cex, off);
    }
    __shared__ float acc[32];
    if (lane == 0) {
        float dg = S[w * 33];
        acc[w] = (dg - (rm + logf(re))) + (dg - (cm + logf(cex)));
    }
    __syncthreads();
    if (tid == 0) {
        float t = 0.f;
        for (int i = 0; i < 32; i++) t += acc[i];
        out[0] = -0.5f * t * (1.f / 32.f);
    }
}

// ---------------------------------------------------------------------------
extern "C" void kernel_launch(void* const* d_in, const int* in_sizes, int n_in,
                              void* d_out, int out_size) {
    const float* bef        = (const float*)d_in[0];
    const float* sentf      = (const float*)d_in[1];
    const float* aft        = (const float*)d_in[2];
    const float* masks      = (const float*)d_in[3];
    const float* conv1_w    = (const float*)d_in[4];
    const float* conv1_b    = (const float*)d_in[5];
    const float* in_proj_w  = (const float*)d_in[6];
    const float* out_proj_w = (const float*)d_in[7];
    const float* conv2_w    = (const float*)d_in[8];
    const float* conv2_b    = (const float*)d_in[9];
    const float* q_w        = (const float*)d_in[10];
    const float* q_b        = (const float*)d_in[11];
    const float* k_w        = (const float*)d_in[12];
    const float* k_b        = (const float*)d_in[13];
    const float* logit_scale= (const float*)d_in[14];

    float* base = nullptr;
    cudaGetSymbolAddress((void**)&base, g_buf);
    float* p_sm  = base + OFF_SM;
    float* p_b2  = base + OFF_B2;
    float* p_bq  = base + OFF_BQ;
    float* p_w67 = base + OFF_W67;
    float* p_wq  = base + OFF_WQ;
    float* p_S   = base + OFF_S;
    float* p_v1  = base + OFF_V1;
    float* p_qkv = base + OFF_QKV;
    unsigned* p_rp = (unsigned*)(base + OFF_RP);
    unsigned* p_cp = (unsigned*)(base + OFF_CP);
    #define BF16P(off) ((__nv_bfloat16*)(base + (off)))
    __nv_bfloat16* aoh  = BF16P(OFF_AOH);  __nv_bfloat16* aol  = BF16P(OFF_AOL);
    __nv_bfloat16* afth = BF16P(OFF_AFTH); __nv_bfloat16* aftl = BF16P(OFF_AFTL);
    __nv_bfloat16* qlh  = BF16P(OFF_QLH);  __nv_bfloat16* qll  = BF16P(OFF_QLL);
    __nv_bfloat16* klh  = BF16P(OFF_KLH);  __nv_bfloat16* kll  = BF16P(OFF_KLL);
    __nv_bfloat16* wqh  = BF16P(OFF_WQH);  __nv_bfloat16* wql  = BF16P(OFF_WQL);
    __nv_bfloat16* kwh  = BF16P(OFF_KWH);  __nv_bfloat16* kwl  = BF16P(OFF_KWL);

    cudaFuncSetAttribute(mma_gemm_b1, cudaFuncAttributeMaxDynamicSharedMemorySize, MG_SMEM);
    cudaFuncSetAttribute(pair_mma_kernel, cudaFuncAttributeMaxDynamicSharedMemorySize, PK_SMEM);

    // prep: text mean, per-batch conv1 bias, init partials, aft/k_w splits
    sent_mean_kernel<<<32, 512>>>(sentf, masks, p_sm);
    bias2_kernel<<<2048, 256>>>(conv1_w, conv1_b, p_sm, p_b2);
    init_parts_kernel<<<256, 256>>>(p_rp, 2 * 200704);
    split_vec_kernel<<<512, 256>>>((const float4*)aft, (uint2*)afth, (uint2*)aftl, 6272 * 128);
    split_vec_kernel<<<256, 256>>>((const float4*)k_w, (uint2*)kwh, (uint2*)kwl, 512 * 128);

    // v1 = bef @ conv1_w[:, :512]^T + bias2[b]   (exact fp32)
    gemm128<2><<<dim3(4, 49), 256>>>(bef, conv1_w, p_v1, p_b2, 512, 512, 1024, 512);
    // qkv = v1 @ in_proj_w^T                     (exact fp32)
    gemm128<0><<<dim3(12, 49), 256>>>(p_v1, in_proj_w, p_qkv, nullptr, 512, 512, 512, 1536);

    size_t attn_smem = (2 * 196 * 65 + 8 * 256) * sizeof(float);
    cudaFuncSetAttribute(attn_kernel, cudaFuncAttributeMaxDynamicSharedMemorySize, (int)attn_smem);
    attn_kernel<<<256, 256, attn_smem>>>(p_qkv, aoh, aol);

    // fused weights: Wq = q_w @ conv2_w @ out_proj_w ; bq = q_b + q_w@conv2_b
    gemm64_nt<<<dim3(8, 8), 256>>>(conv2_w, out_proj_w, p_w67, 512, 512, 512, 512);
    gemm64_nt<<<dim3(8, 8), 256>>>(q_w, p_w67, p_wq, 512, 512, 512, 512);
    bq_kernel<<<64, 256>>>(q_w, conv2_b, q_b, p_bq);
    split_vec_kernel<<<256, 256>>>((const float4*)p_wq, (uint2*)wqh, (uint2*)wql, 512 * 128);

    // QL = ao @ Wq^T + bq ; KL = aft @ k_w^T + k_b   (bf16x3 mma, split out)
    mma_gemm_b1<<<dim3(4, 49), 256, MG_SMEM>>>(aoh, aol, wqh, wql, qlh, qll, p_bq);
    mma_gemm_b1<<<dim3(4, 49), 256, MG_SMEM>>>(afth, aftl, kwh, kwl, klh, kll, k_b);

    // pair GEMM + fused max epilogue (cp.async double-buffered)
    pair_mma_kernel<<<dim3(49, 49), 256, PK_SMEM>>>(qlh, qll, klh, kll, p_rp, p_cp);

    reduce_s_kernel<<<1024, 256>>>(p_rp, p_cp, logit_scale, p_S);
    loss_kernel<<<1, 1024>>>(p_S, (float*)d_out);
}

// round 12
// speedup vs baseline: 1.0230x; 1.0230x over previous
#include <cuda_runtime.h>
#include <cuda_bf16.h>
#include <math.h>
#include <stdint.h>

// Shapes fixed: B=32, LV=196, LT=40, D=512, H=8, DH=64, R=B*LV=6272 (=49*128)

// ---------------------------------------------------------------------------
// Scratch buffer layout (float slots)
// ---------------------------------------------------------------------------
#define OFF_SM    0u
#define OFF_B2    16384u
#define OFF_BQ    32768u
#define OFF_W67   33280u
#define OFF_WQ    295424u
#define OFF_S     557568u
#define OFF_RP    558592u
#define OFF_CP    759296u
#define OFF_WC    960000u    // Wcomb 1536x512 = 786432
#define OFF_BQK   1746432u   // biasq 32x1536 = 49152
#define OFF_QKV   1795584u   // 9633792 fp32
#define OFF_AOH   11429376u
#define OFF_AOL   13035008u
#define OFF_AFTH  14640640u
#define OFF_AFTL  16246272u
#define OFF_QLH   17851904u
#define OFF_QLL   19457536u
#define OFF_KLH   21063168u
#define OFF_KLL   22668800u
#define OFF_WQH   24274432u
#define OFF_WQL   24339968u
#define OFF_KWH   24405504u
#define OFF_KWL   24471040u
#define TOTAL_F   24536576u

__device__ __align__(256) float g_buf[TOTAL_F];

// ---------------------------------------------------------------------------
// mma.sync / ldmatrix / cp.async helpers
// ---------------------------------------------------------------------------
__device__ __forceinline__ uint32_t smem_u32(const void* p) {
    uint32_t a;
    asm("{ .reg .u64 t; cvta.to.shared.u64 t, %1; cvt.u32.u64 %0, t; }" : "=r"(a) : "l"(p));
    return a;
}
__device__ __forceinline__ void ldsm_x4(uint32_t* r, uint32_t addr) {
    asm volatile("ldmatrix.sync.aligned.m8n8.x4.shared.b16 {%0,%1,%2,%3}, [%4];"
                 : "=r"(r[0]), "=r"(r[1]), "=r"(r[2]), "=r"(r[3]) : "r"(addr));
}
__device__ __forceinline__ void ldsm_x2(uint32_t* r, uint32_t addr) {
    asm volatile("ldmatrix.sync.aligned.m8n8.x2.shared.b16 {%0,%1}, [%2];"
                 : "=r"(r[0]), "=r"(r[1]) : "r"(addr));
}
__device__ __forceinline__ void mma_bf16(float* d, const uint32_t* a, const uint32_t* b) {
    asm volatile("mma.sync.aligned.m16n8k16.row.col.f32.bf16.bf16.f32 "
                 "{%0,%1,%2,%3}, {%4,%5,%6,%7}, {%8,%9}, {%0,%1,%2,%3};"
                 : "+f"(d[0]), "+f"(d[1]), "+f"(d[2]), "+f"(d[3])
                 : "r"(a[0]), "r"(a[1]), "r"(a[2]), "r"(a[3]), "r"(b[0]), "r"(b[1]));
}
__device__ __forceinline__ void cp_async16(uint32_t dst, const void* src) {
    asm volatile("cp.async.cg.shared.global [%0], [%1], 16;" :: "r"(dst), "l"(src) : "memory");
}
__device__ __forceinline__ void cp_commit() {
    asm volatile("cp.async.commit_group;" ::: "memory");
}
template<int N>
__device__ __forceinline__ void cp_wait() {
    asm volatile("cp.async.wait_group %0;" :: "n"(N) : "memory");
}
#define SWZ128(off) ((off) ^ (((off) >> 3) & 0x70))

__device__ __forceinline__ unsigned enc_f(float f) {
    unsigned u = __float_as_uint(f);
    return u ^ ((((int)u >> 31)) | 0x80000000u);
}
__device__ __forceinline__ float dec_f(unsigned u) {
    unsigned m = (u & 0x80000000u) ? 0x80000000u : 0xFFFFFFFFu;
    return __uint_as_float(u ^ m);
}

// ---------------------------------------------------------------------------
__global__ void sent_mean_kernel(const float* __restrict__ sentf,
                                 const float* __restrict__ masks,
                                 float* __restrict__ sm) {
    int b = blockIdx.x, d = threadIdx.x;
    float s = 0.f;
    #pragma unroll
    for (int t = 0; t < 40; t++)
        s += sentf[(b * 40 + t) * 512 + d] * masks[b * 40 + t];
    sm[b * 512 + d] = s * (1.f / 40.f);
}

__global__ void bias2_kernel(const float* __restrict__ conv1_w,
                             const float* __restrict__ conv1_b,
                             const float* __restrict__ sm,
                             float* __restrict__ b2) {
    int gw = (blockIdx.x * blockDim.x + threadIdx.x) >> 5;
    int lane = threadIdx.x & 31;
    int b = gw >> 9, o = gw & 511;
    const float* wrow = conv1_w + o * 1024 + 512;
    const float* srow = sm + b * 512;
    float s = 0.f;
    for (int c = lane; c < 512; c += 32) s += wrow[c] * srow[c];
    #pragma unroll
    for (int off = 16; off; off >>= 1) s += __shfl_xor_sync(0xffffffffu, s, off);
    if (lane == 0) b2[b * 512 + o] = conv1_b[o] + s;
}

// biasq[b][e] = sum_k b2[b,k] * in_proj[e,k]   (warp per output, 32x1536)
__global__ void biasq_kernel(const float* __restrict__ b2,
                             const float* __restrict__ in_proj,
                             float* __restrict__ biasq) {
    int gw = blockIdx.x * 8 + (threadIdx.x >> 5);   // 0..49151
    int lane = threadIdx.x & 31;
    int b = gw / 1536, e = gw % 1536;
    const float* brow = b2 + b * 512;
    const float* wrow = in_proj + e * 512;
    float s = 0.f;
    for (int c = lane; c < 512; c += 32) s += brow[c] * wrow[c];
    #pragma unroll
    for (int off = 16; off; off >>= 1) s += __shfl_xor_sync(0xffffffffu, s, off);
    if (lane == 0) biasq[gw] = s;
}

// warp-per-output: bq[q] = q_b[q] + sum_o q_w[q,o]*conv2_b[o]
__global__ void bq_kernel(const float* __restrict__ q_w,
                          const float* __restrict__ conv2_b,
                          const float* __restrict__ q_b,
                          float* __restrict__ bq) {
    int gw = blockIdx.x * 8 + (threadIdx.x >> 5);
    int lane = threadIdx.x & 31;
    const float* row = q_w + gw * 512;
    float s = 0.f;
    for (int c = lane; c < 512; c += 32) s += row[c] * conv2_b[c];
    #pragma unroll
    for (int off = 16; off; off >>= 1) s += __shfl_xor_sync(0xffffffffu, s, off);
    if (lane == 0) bq[gw] = q_b[gw] + s;
}

// ---------------------------------------------------------------------------
// Small fp32 GEMM for weight fusions. C = A(MxK)*B(KxN) (both row-major).
// ---------------------------------------------------------------------------
__global__ void gemm64_nt(const float* __restrict__ A, const float* __restrict__ B,
                          float* __restrict__ C, int K, int lda, int ldb, int ldc) {
    __shared__ float As[32][65];
    __shared__ float Bs[32][65];
    int tid = threadIdx.x;
    int tx = tid & 15, ty = tid >> 4;
    int n0 = blockIdx.x * 64, m0 = blockIdx.y * 64;
    float acc[4][4] = {};
    for (int k0 = 0; k0 < K; k0 += 32) {
        #pragma unroll
        for (int i = 0; i < 8; i++) {
            int idx = tid + i * 256;
            int k = idx & 31, r = idx >> 5;
            As[k][r] = A[(m0 + r) * lda + k0 + k];
            int n = idx & 63, kk = idx >> 6;
            Bs[kk][n] = B[(k0 + kk) * ldb + n0 + n];
        }
        __syncthreads();
        #pragma unroll
        for (int k = 0; k < 32; k++) {
            float ar[4], br[4];
            #pragma unroll
            for (int i = 0; i < 4; i++) ar[i] = As[k][ty * 4 + i];
            #pragma unroll
            for (int j = 0; j < 4; j++) br[j] = Bs[k][tx * 4 + j];
            #pragma unroll
            for (int i = 0; i < 4; i++)
                #pragma unroll
                for (int j = 0; j < 4; j++) acc[i][j] += ar[i] * br[j];
        }
        __syncthreads();
    }
    #pragma unroll
    for (int i = 0; i < 4; i++)
        #pragma unroll
        for (int j = 0; j < 4; j++)
            C[(m0 + ty * 4 + i) * ldc + n0 + tx * 4 + j] = acc[i][j];
}

// ---------------------------------------------------------------------------
// fp32 SIMT GEMM: C = A(MxK) * B(NxK)^T, 128x128 tile, 8x8 micro, BK=16, dbuf.
// MODE 0: plain. MODE 2: +bias[(r/196)*biasld + n].
// ---------------------------------------------------------------------------
template<int MODE>
__global__ void __launch_bounds__(256) gemm128(
        const float* __restrict__ A, const float* __restrict__ B,
        float* __restrict__ C, const float* __restrict__ bias,
        int K, int lda, int ldb, int ldc, int biasld) {
    __shared__ float As[2][16][132];
    __shared__ float Bs[2][16][132];
    int tid = threadIdx.x;
    int tx = tid & 15, ty = tid >> 4;
    int row = tid >> 1, seg = tid & 1;
    int m0 = blockIdx.y * 128, n0 = blockIdx.x * 128;

    const float* Abase = A + (m0 + row) * lda + seg * 8;
    const float* Bbase = B + (n0 + row) * ldb + seg * 8;

    float acc[8][8] = {};
    float4 pa0 = *(const float4*)Abase;
    float4 pa1 = *(const float4*)(Abase + 4);
    float4 pb0 = *(const float4*)Bbase;
    float4 pb1 = *(const float4*)(Bbase + 4);
    As[0][seg * 8 + 0][row] = pa0.x; As[0][seg * 8 + 1][row] = pa0.y;
    As[0][seg * 8 + 2][row] = pa0.z; As[0][seg * 8 + 3][row] = pa0.w;
    As[0][seg * 8 + 4][row] = pa1.x; As[0][seg * 8 + 5][row] = pa1.y;
    As[0][seg * 8 + 6][row] = pa1.z; As[0][seg * 8 + 7][row] = pa1.w;
    Bs[0][seg * 8 + 0][row] = pb0.x; Bs[0][seg * 8 + 1][row] = pb0.y;
    Bs[0][seg * 8 + 2][row] = pb0.z; Bs[0][seg * 8 + 3][row] = pb0.w;
    Bs[0][seg * 8 + 4][row] = pb1.x; Bs[0][seg * 8 + 5][row] = pb1.y;
    Bs[0][seg * 8 + 6][row] = pb1.z; Bs[0][seg * 8 + 7][row] = pb1.w;
    __syncthreads();

    int NK = K >> 4;
    for (int kt = 0; kt < NK; kt++) {
        int cur = kt & 1;
        if (kt + 1 < NK) {
            pa0 = *(const float4*)(Abase + (kt + 1) * 16);
            pa1 = *(const float4*)(Abase + (kt + 1) * 16 + 4);
            pb0 = *(const float4*)(Bbase + (kt + 1) * 16);
            pb1 = *(const float4*)(Bbase + (kt + 1) * 16 + 4);
        }
        #pragma unroll
        for (int k = 0; k < 16; k++) {
            float ar[8], br[8];
            *(float4*)(ar)     = *(const float4*)&As[cur][k][ty * 4];
            *(float4*)(ar + 4) = *(const float4*)&As[cur][k][64 + ty * 4];
            *(float4*)(br)     = *(const float4*)&Bs[cur][k][tx * 4];
            *(float4*)(br + 4) = *(const float4*)&Bs[cur][k][64 + tx * 4];
            #pragma unroll
            for (int i = 0; i < 8; i++)
                #pragma unroll
                for (int j = 0; j < 8; j++)
                    acc[i][j] += ar[i] * br[j];
        }
        if (kt + 1 < NK) {
            int nxt = cur ^ 1;
            As[nxt][seg * 8 + 0][row] = pa0.x; As[nxt][seg * 8 + 1][row] = pa0.y;
            As[nxt][seg * 8 + 2][row] = pa0.z; As[nxt][seg * 8 + 3][row] = pa0.w;
            As[nxt][seg * 8 + 4][row] = pa1.x; As[nxt][seg * 8 + 5][row] = pa1.y;
            As[nxt][seg * 8 + 6][row] = pa1.z; As[nxt][seg * 8 + 7][row] = pa1.w;
            Bs[nxt][seg * 8 + 0][row] = pb0.x; Bs[nxt][seg * 8 + 1][row] = pb0.y;
            Bs[nxt][seg * 8 + 2][row] = pb0.z; Bs[nxt][seg * 8 + 3][row] = pb0.w;
            Bs[nxt][seg * 8 + 4][row] = pb1.x; Bs[nxt][seg * 8 + 5][row] = pb1.y;
            Bs[nxt][seg * 8 + 6][row] = pb1.z; Bs[nxt][seg * 8 + 7][row] = pb1.w;
        }
        __syncthreads();
    }

    #pragma unroll
    for (int i = 0; i < 8; i++) {
        int r = m0 + ty * 4 + (i & 3) + ((i >> 2) << 6);
        int boff = (MODE == 2) ? (r / 196) * biasld : 0;
        #pragma unroll
        for (int hj = 0; hj < 2; hj++) {
            int c = n0 + tx * 4 + (hj << 6);
            float4 v;
            v.x = acc[i][hj * 4 + 0]; v.y = acc[i][hj * 4 + 1];
            v.z = acc[i][hj * 4 + 2]; v.w = acc[i][hj * 4 + 3];
            if (MODE == 2) {
                v.x += bias[boff + c]; v.y += bias[boff + c + 1];
                v.z += bias[boff + c + 2]; v.w += bias[boff + c + 3];
            }
            *(float4*)&C[r * ldc + c] = v;
        }
    }
}

// ---------------------------------------------------------------------------
// Vectorized split: hi = bf16(x), lo = bf16(x - hi). Contiguous, n % 4 == 0.
// ---------------------------------------------------------------------------
__global__ void split_vec_kernel(const float4* __restrict__ src,
                                 uint2* __restrict__ hi,
                                 uint2* __restrict__ lo, int n4) {
    for (int i = blockIdx.x * blockDim.x + threadIdx.x; i < n4; i += gridDim.x * blockDim.x) {
        float4 x = src[i];
        __nv_bfloat162 h0, h1, l0, l1;
        h0.x = __float2bfloat16(x.x); h0.y = __float2bfloat16(x.y);
        h1.x = __float2bfloat16(x.z); h1.y = __float2bfloat16(x.w);
        l0.x = __float2bfloat16(x.x - __bfloat162float(h0.x));
        l0.y = __float2bfloat16(x.y - __bfloat162float(h0.y));
        l1.x = __float2bfloat16(x.z - __bfloat162float(h1.x));
        l1.y = __float2bfloat16(x.w - __bfloat162float(h1.y));
        hi[i] = make_uint2(*(uint32_t*)&h0, *(uint32_t*)&h1);
        lo[i] = make_uint2(*(uint32_t*)&l0, *(uint32_t*)&l1);
    }
}

__global__ void init_parts_kernel(unsigned* __restrict__ p, int n) {
    for (int i = blockIdx.x * blockDim.x + threadIdx.x; i < n; i += gridDim.x * blockDim.x)
        p[i] = 0x007FFFFFu;   // enc(-inf)
}

// ---------------------------------------------------------------------------
// bf16x3 mma GEMM (MODE 1): C[M,N] = A(Mx512)@W(Nx512)^T + bias[n],
// output as bf16 hi/lo splits. 128x128 CTA tile, 8 warps x (64x32).
// ---------------------------------------------------------------------------
#define MG_SMEM 65536
#define SM_AH 0
#define SM_AL 16384
#define SM_BH 32768
#define SM_BL 49152

__global__ void __launch_bounds__(256) mma_gemm_b1(
        const __nv_bfloat16* __restrict__ Ah, const __nv_bfloat16* __restrict__ Al,
        const __nv_bfloat16* __restrict__ Wh, const __nv_bfloat16* __restrict__ Wl,
        __nv_bfloat16* __restrict__ outh, __nv_bfloat16* __restrict__ outl,
        const float* __restrict__ bias) {
    extern __shared__ char smem[];
    int tid = threadIdx.x;
    int wid = tid >> 5, lane = tid & 31;
    int m0 = blockIdx.y * 128, n0 = blockIdx.x * 128;
    int wm0 = (wid >> 2) * 64, wn0 = (wid & 3) * 32;

    int a_row = wm0 + (lane & 15);
    int a_ch  = (lane >> 4);
    int b_row = wn0 + (lane & 7);
    int b_ch  = ((lane >> 3) & 1);
    uint32_t smem_b = smem_u32(smem);

    float d[4][4][4];
    #pragma unroll
    for (int i = 0; i < 4; i++)
        #pragma unroll
        for (int j = 0; j < 4; j++)
            #pragma unroll
            for (int q = 0; q < 4; q++) d[i][j][q] = 0.f;

    for (int kc = 0; kc < 8; kc++) {
        __syncthreads();
        #pragma unroll
        for (int t = 0; t < 4; t++) {
            int s2 = tid + t * 256;
            int row = s2 >> 3, sc = s2 & 7;
            uint32_t sw = SWZ128((uint32_t)(row * 128 + sc * 16));
            long ga = (long)(m0 + row) * 512 + kc * 64 + sc * 8;
            long gb = (long)(n0 + row) * 512 + kc * 64 + sc * 8;
            *(uint4*)(smem + SM_AH + sw) = *(const uint4*)(Ah + ga);
            *(uint4*)(smem + SM_AL + sw) = *(const uint4*)(Al + ga);
            *(uint4*)(smem + SM_BH + sw) = *(const uint4*)(Wh + gb);
            *(uint4*)(smem + SM_BL + sw) = *(const uint4*)(Wl + gb);
        }
        __syncthreads();

        #pragma unroll
        for (int ks = 0; ks < 4; ks++) {
            int ach = (ks * 2 + a_ch) ^ (a_row & 7);
            int bch = (ks * 2 + b_ch) ^ (b_row & 7);
            uint32_t ah[4][4], bh[4][2], bl[4][2], al[4][4];
            #pragma unroll
            for (int i = 0; i < 4; i++)
                ldsm_x4(ah[i], smem_b + SM_AH + (a_row + i * 16) * 128 + ach * 16);
            #pragma unroll
            for (int j = 0; j < 4; j++)
                ldsm_x2(bh[j], smem_b + SM_BH + (b_row + j * 8) * 128 + bch * 16);
            #pragma unroll
            for (int i = 0; i < 4; i++)
                #pragma unroll
                for (int j = 0; j < 4; j++) mma_bf16(d[i][j], ah[i], bh[j]);
            #pragma unroll
            for (int j = 0; j < 4; j++)
                ldsm_x2(bl[j], smem_b + SM_BL + (b_row + j * 8) * 128 + bch * 16);
            #pragma unroll
            for (int i = 0; i < 4; i++)
                #pragma unroll
                for (int j = 0; j < 4; j++) mma_bf16(d[i][j], ah[i], bl[j]);
            #pragma unroll
            for (int i = 0; i < 4; i++)
                ldsm_x4(al[i], smem_b + SM_AL + (a_row + i * 16) * 128 + ach * 16);
            #pragma unroll
            for (int i = 0; i < 4; i++)
                #pragma unroll
                for (int j = 0; j < 4; j++) mma_bf16(d[i][j], al[i], bh[j]);
        }
    }

    int fr = lane >> 2, fc = (lane & 3) * 2;
    #pragma unroll
    for (int i = 0; i < 4; i++) {
        #pragma unroll
        for (int j = 0; j < 4; j++) {
            int gc = n0 + wn0 + j * 8 + fc;
            float b0 = bias[gc], b1 = bias[gc + 1];
            #pragma unroll
            for (int hh = 0; hh < 2; hh++) {
                int gr = m0 + wm0 + i * 16 + fr + hh * 8;
                float v0 = d[i][j][hh * 2 + 0] + b0;
                float v1 = d[i][j][hh * 2 + 1] + b1;
                __nv_bfloat162 hp, lp;
                hp.x = __float2bfloat16(v0);
                hp.y = __float2bfloat16(v1);
                lp.x = __float2bfloat16(v0 - __bfloat162float(hp.x));
                lp.y = __float2bfloat16(v1 - __bfloat162float(hp.y));
                *(uint32_t*)&outh[(long)gr * 512 + gc] = *(uint32_t*)&hp;
                *(uint32_t*)&outl[(long)gr * 512 + gc] = *(uint32_t*)&lp;
            }
        }
    }
}

// ---------------------------------------------------------------------------
// Attention: one CTA per (b,h). 4 query rows per warp iteration, d-outer QK.
// ---------------------------------------------------------------------------
__global__ void attn_kernel(const float* __restrict__ qkv,
                            __nv_bfloat16* __restrict__ outh,
                            __nv_bfloat16* __restrict__ outl) {
    int b = blockIdx.x >> 3, h = blockIdx.x & 7;
    extern __shared__ float smemf[];
    float* ks = smemf;                    // 196*65
    float* vs = smemf + 196 * 65;         // 196*65
    float* qs = smemf + 2 * 196 * 65;     // 8*256
    int tid = threadIdx.x;
    const float* base = qkv + b * (196 * 1536) + h * 64;
    for (int idx = tid; idx < 196 * 64; idx += 256) {
        int m = idx >> 6, d = idx & 63;
        ks[m * 65 + d] = base[m * 1536 + 512 + d];
        vs[m * 65 + d] = base[m * 1536 + 1024 + d];
    }
    __syncthreads();
    int w = tid >> 5, lane = tid & 31;
    float* q0 = qs + w * 256;

    for (int l0 = w; l0 < 196; l0 += 32) {
        bool has[4];
        #pragma unroll
        for (int rr = 0; rr < 4; rr++) {
            int lr = l0 + rr * 8;
            has[rr] = lr < 196;
            if (has[rr]) {
                q0[rr * 64 + lane]      = base[lr * 1536 + lane];
                q0[rr * 64 + lane + 32] = base[lr * 1536 + lane + 32];
            } else {
                q0[rr * 64 + lane]      = 0.f;
                q0[rr * 64 + lane + 32] = 0.f;
            }
        }
        __syncwarp();

        float s[4][7];
        #pragma unroll
        for (int rr = 0; rr < 4; rr++)
            #pragma unroll
            for (int j = 0; j < 7; j++) s[rr][j] = 0.f;

        for (int d = 0; d < 64; d++) {
            float kv[7];
            #pragma unroll
            for (int j = 0; j < 6; j++) kv[j] = ks[(j * 32 + lane) * 65 + d];
            kv[6] = (lane < 4) ? ks[(192 + lane) * 65 + d] : 0.f;
            #pragma unroll
            for (int rr = 0; rr < 4; rr++) {
                float qv = q0[rr * 64 + d];
                #pragma unroll
                for (int j = 0; j < 7; j++) s[rr][j] += qv * kv[j];
            }
        }
        #pragma unroll
        for (int rr = 0; rr < 4; rr++) {
            #pragma unroll
            for (int j = 0; j < 7; j++) s[rr][j] *= 0.125f;
            if (lane >= 4) s[rr][6] = -INFINITY;
        }

        float inv[4];
        #pragma unroll
        for (int rr = 0; rr < 4; rr++) {
            float mx = s[rr][0];
            #pragma unroll
            for (int j = 1; j < 7; j++) mx = fmaxf(mx, s[rr][j]);
            #pragma unroll
            for (int off = 16; off; off >>= 1)
                mx = fmaxf(mx, __shfl_xor_sync(0xffffffffu, mx, off));
            float sum = 0.f;
            #pragma unroll
            for (int j = 0; j < 7; j++) { s[rr][j] = expf(s[rr][j] - mx); sum += s[rr][j]; }
            #pragma unroll
            for (int off = 16; off; off >>= 1)
                sum += __shfl_xor_sync(0xffffffffu, sum, off);
            inv[rr] = 1.f / sum;
        }

        float o0[4] = {0.f, 0.f, 0.f, 0.f};
        float o1[4] = {0.f, 0.f, 0.f, 0.f};
        #pragma unroll
        for (int j = 0; j < 7; j++) {
            #pragma unroll
            for (int mm = 0; mm < 32; mm++) {
                int m = j * 32 + mm;
                if (m >= 196) break;
                float v0 = vs[m * 65 + lane];
                float v1 = vs[m * 65 + lane + 32];
                #pragma unroll
                for (int rr = 0; rr < 4; rr++) {
                    float p = __shfl_sync(0xffffffffu, s[rr][j], mm);
                    o0[rr] += p * v0;
                    o1[rr] += p * v1;
                }
            }
        }
        #pragma unroll
        for (int rr = 0; rr < 4; rr++) {
            if (!has[rr]) continue;
            int r = b * 196 + l0 + rr * 8;
            float x0 = o0[rr] * inv[rr], x1 = o1[rr] * inv[rr];
            long i0 = (long)r * 512 + h * 64 + lane;
            __nv_bfloat16 h0 = __float2bfloat16(x0);
            __nv_bfloat16 h1 = __float2bfloat16(x1);
            outh[i0]      = h0;
            outh[i0 + 32] = h1;
            outl[i0]      = __float2bfloat16(x0 - __bfloat162float(h0));
            outl[i0 + 32] = __float2bfloat16(x1 - __bfloat162float(h1));
        }
        __syncwarp();
    }
}

// ---------------------------------------------------------------------------
// Pair kernel via mma.sync bf16x3 with fused row/col max epilogue.
// 2-stage cp.async pipeline (2 x 64KB smem buffers).
// ---------------------------------------------------------------------------
#define PK_SMEM 131072
#define PK_BUF  65536

__global__ void __launch_bounds__(256) pair_mma_kernel(
        const __nv_bfloat16* __restrict__ QLh, const __nv_bfloat16* __restrict__ QLl,
        const __nv_bfloat16* __restrict__ KLh, const __nv_bfloat16* __restrict__ KLl,
        unsigned* __restrict__ rowparts, unsigned* __restrict__ colparts) {
    extern __shared__ char smem[];
    float (*Ct)[130] = (float(*)[130])smem;
    int tid = threadIdx.x;
    int wid = tid >> 5, lane = tid & 31;
    int m0 = blockIdx.y * 128, n0 = blockIdx.x * 128;
    int wm0 = (wid >> 2) * 64, wn0 = (wid & 3) * 32;

    int a_row = wm0 + (lane & 15);
    int a_ch  = (lane >> 4);
    int b_row = wn0 + (lane & 7);
    int b_ch  = ((lane >> 3) & 1);
    uint32_t smem_b = smem_u32(smem);

    float d[4][4][4];
    #pragma unroll
    for (int i = 0; i < 4; i++)
        #pragma unroll
        for (int j = 0; j < 4; j++)
            #pragma unroll
            for (int q = 0; q < 4; q++) d[i][j][q] = 0.f;

    auto stage = [&](int kc, int buf) {
        uint32_t b0 = smem_b + buf * PK_BUF;
        #pragma unroll
        for (int t = 0; t < 4; t++) {
            int s2 = tid + t * 256;
            int row = s2 >> 3, sc = s2 & 7;
            uint32_t sw = SWZ128((uint32_t)(row * 128 + sc * 16));
            long ga = (long)(m0 + row) * 512 + kc * 64 + sc * 8;
            long gb = (long)(n0 + row) * 512 + kc * 64 + sc * 8;
            cp_async16(b0 + SM_AH + sw, QLh + ga);
            cp_async16(b0 + SM_AL + sw, QLl + ga);
            cp_async16(b0 + SM_BH + sw, KLh + gb);
            cp_async16(b0 + SM_BL + sw, KLl + gb);
        }
        cp_commit();
    };

    stage(0, 0);
    for (int kc = 0; kc < 8; kc++) {
        if (kc < 7) stage(kc + 1, (kc + 1) & 1);
        if (kc < 7) cp_wait<1>(); else cp_wait<0>();
        __syncthreads();
        uint32_t bofs = (uint32_t)((kc & 1) * PK_BUF);

        #pragma unroll
        for (int ks = 0; ks < 4; ks++) {
            int ach = (ks * 2 + a_ch) ^ (a_row & 7);
            int bch = (ks * 2 + b_ch) ^ (b_row & 7);
            uint32_t ah[4][4], bh[4][2], bl[4][2], al[4][4];
            #pragma unroll
            for (int i = 0; i < 4; i++)
                ldsm_x4(ah[i], smem_b + bofs + SM_AH + (a_row + i * 16) * 128 + ach * 16);
            #pragma unroll
            for (int j = 0; j < 4; j++)
                ldsm_x2(bh[j], smem_b + bofs + SM_BH + (b_row + j * 8) * 128 + bch * 16);
            #pragma unroll
            for (int i = 0; i < 4; i++)
                #pragma unroll
                for (int j = 0; j < 4; j++) mma_bf16(d[i][j], ah[i], bh[j]);
            #pragma unroll
            for (int j = 0; j < 4; j++)
                ldsm_x2(bl[j], smem_b + bofs + SM_BL + (b_row + j * 8) * 128 + bch * 16);
            #pragma unroll
            for (int i = 0; i < 4; i++)
                #pragma unroll
                for (int j = 0; j < 4; j++) mma_bf16(d[i][j], ah[i], bl[j]);
            #pragma unroll
            for (int i = 0; i < 4; i++)
                ldsm_x4(al[i], smem_b + bofs + SM_AL + (a_row + i * 16) * 128 + ach * 16);
            #pragma unroll
            for (int i = 0; i < 4; i++)
                #pragma unroll
                for (int j = 0; j < 4; j++) mma_bf16(d[i][j], al[i], bh[j]);
        }
        __syncthreads();
    }

    int fr = lane >> 2, fc = (lane & 3) * 2;
    #pragma unroll
    for (int i = 0; i < 4; i++) {
        #pragma unroll
        for (int j = 0; j < 4; j++) {
            int r = wm0 + i * 16 + fr, c = wn0 + j * 8 + fc;
            *(float2*)&Ct[r][c]     = make_float2(d[i][j][0], d[i][j][1]);
            *(float2*)&Ct[r + 8][c] = make_float2(d[i][j][2], d[i][j][3]);
        }
    }
    __syncthreads();

    if (tid < 128) {
        int r = tid, gr = m0 + r;
        int b0 = n0 / 196;
        int bnd = (b0 + 1) * 196 - n0;
        if (bnd > 128) bnd = 128;
        float m1 = -INFINITY, m2 = -INFINITY;
        for (int c = 0; c < 128; c++) {
            float v = Ct[r][c];
            if (c < bnd) m1 = fmaxf(m1, v); else m2 = fmaxf(m2, v);
        }
        atomicMax(&rowparts[b0 * 6272 + gr], enc_f(m1));
        if (bnd < 128)
            atomicMax(&rowparts[(b0 + 1) * 6272 + gr], enc_f(m2));
    } else {
        int c = tid - 128, gc = n0 + c;
        int a0 = m0 / 196;
        int bnd = (a0 + 1) * 196 - m0;
        if (bnd > 128) bnd = 128;
        float m1 = -INFINITY, m2 = -INFINITY;
        for (int r = 0; r < 128; r++) {
            float v = Ct[r][c];
            if (r < bnd) m1 = fmaxf(m1, v); else m2 = fmaxf(m2, v);
        }
        atomicMax(&colparts[a0 * 6272 + gc], enc_f(m1));
        if (bnd < 128)
            atomicMax(&colparts[(a0 + 1) * 6272 + gc], enc_f(m2));
    }
}

// ---------------------------------------------------------------------------
__global__ void reduce_s_kernel(const unsigned* __restrict__ rowparts,
                                const unsigned* __restrict__ colparts,
                                const float* __restrict__ logit_scale,
                                float* __restrict__ S) {
    int pair = blockIdx.x, tid = threadIdx.x;
    int a = pair >> 5, b = pair & 31;
    float s = 0.f;
    for (int l = tid; l < 196; l += 256)
        s += dec_f(rowparts[b * 6272 + a * 196 + l]);
    for (int m = tid; m < 196; m += 256)
        s += dec_f(colparts[a * 6272 + b * 196 + m]);
    __shared__ float red[256];
    red[tid] = s;
    __syncthreads();
    for (int st = 128; st; st >>= 1) {
        if (tid < st) red[tid] += red[tid + st];
        __syncthreads();
    }
    if (tid == 0) S[pair] = 0.5f * red[0] * (1.f / 196.f) * expf(logit_scale[0]);
}

__global__ void loss_kernel(const float* __restrict__ S, float* __restrict__ out) {
    int tid = threadIdx.x;
    int w = tid >> 5, lane = tid & 31;
    float rv = S[w * 32 + lane];
    float cv = S[lane * 32 + w];
    float rm = rv, cm = cv;
    #pragma unroll
    for (int off = 16; off; off >>= 1) {
        rm = fmaxf(rm, __shfl_xor_sync(0xffffffffu, rm, off));
        cm = fmaxf(cm, __shfl_xor_sync(0xffffffffu, cm, off));
    }
    float re = expf(rv - rm), cex = expf(cv - cm);
    #pragma unroll
    for (int off = 16; off; off >>= 1) {
        re  += __shfl_xor_sync(0xffffffffu, re, off);
        cex += __shfl_xor_sync(0xffffffffu, cex, off);
    }
    __shared__ float acc[32];
    if (lane == 0) {
        float dg = S[w * 33];
        acc[w] = (dg - (rm + logf(re))) + (dg - (cm + logf(cex)));
    }
    __syncthreads();
    if (tid == 0) {
        float t = 0.f;
        for (int i = 0; i < 32; i++) t += acc[i];
        out[0] = -0.5f * t * (1.f / 32.f);
    }
}

// ---------------------------------------------------------------------------
extern "C" void kernel_launch(void* const* d_in, const int* in_sizes, int n_in,
                              void* d_out, int out_size) {
    const float* bef        = (const float*)d_in[0];
    const float* sentf      = (const float*)d_in[1];
    const float* aft        = (const float*)d_in[2];
    const float* masks      = (const float*)d_in[3];
    const float* conv1_w    = (const float*)d_in[4];
    const float* conv1_b    = (const float*)d_in[5];
    const float* in_proj_w  = (const float*)d_in[6];
    const float* out_proj_w = (const float*)d_in[7];
    const float* conv2_w    = (const float*)d_in[8];
    const float* conv2_b    = (const float*)d_in[9];
    const float* q_w        = (const float*)d_in[10];
    const float* q_b        = (const float*)d_in[11];
    const float* k_w        = (const float*)d_in[12];
    const float* k_b        = (const float*)d_in[13];
    const float* logit_scale= (const float*)d_in[14];

    float* base = nullptr;
    cudaGetSymbolAddress((void**)&base, g_buf);
    float* p_sm  = base + OFF_SM;
    float* p_b2  = base + OFF_B2;
    float* p_bq  = base + OFF_BQ;
    float* p_w67 = base + OFF_W67;
    float* p_wq  = base + OFF_WQ;
    float* p_S   = base + OFF_S;
    float* p_wc  = base + OFF_WC;
    float* p_bqk = base + OFF_BQK;
    float* p_qkv = base + OFF_QKV;
    unsigned* p_rp = (unsigned*)(base + OFF_RP);
    unsigned* p_cp = (unsigned*)(base + OFF_CP);
    #define BF16P(off) ((__nv_bfloat16*)(base + (off)))
    __nv_bfloat16* aoh  = BF16P(OFF_AOH);  __nv_bfloat16* aol  = BF16P(OFF_AOL);
    __nv_bfloat16* afth = BF16P(OFF_AFTH); __nv_bfloat16* aftl = BF16P(OFF_AFTL);
    __nv_bfloat16* qlh  = BF16P(OFF_QLH);  __nv_bfloat16* qll  = BF16P(OFF_QLL);
    __nv_bfloat16* klh  = BF16P(OFF_KLH);  __nv_bfloat16* kll  = BF16P(OFF_KLL);
    __nv_bfloat16* wqh  = BF16P(OFF_WQH);  __nv_bfloat16* wql  = BF16P(OFF_WQL);
    __nv_bfloat16* kwh  = BF16P(OFF_KWH);  __nv_bfloat16* kwl  = BF16P(OFF_KWL);

    cudaFuncSetAttribute(mma_gemm_b1, cudaFuncAttributeMaxDynamicSharedMemorySize, MG_SMEM);
    cudaFuncSetAttribute(pair_mma_kernel, cudaFuncAttributeMaxDynamicSharedMemorySize, PK_SMEM);

    // prep: text mean, per-batch conv1 bias, init partials, aft/k_w splits
    sent_mean_kernel<<<32, 512>>>(sentf, masks, p_sm);
    bias2_kernel<<<2048, 256>>>(conv1_w, conv1_b, p_sm, p_b2);
    init_parts_kernel<<<256, 256>>>(p_rp, 2 * 200704);
    split_vec_kernel<<<512, 256>>>((const float4*)aft, (uint2*)afth, (uint2*)aftl, 6272 * 128);
    split_vec_kernel<<<256, 256>>>((const float4*)k_w, (uint2*)kwh, (uint2*)kwl, 512 * 128);

    // fold conv1 into in_proj: Wcomb[e,c] = sum_k in_proj[e,k]*conv1_w[k,c] (image half)
    gemm64_nt<<<dim3(8, 24), 256>>>(in_proj_w, conv1_w, p_wc, 512, 512, 1024, 512);
    // biasq[b,e] = b2[b,:] . in_proj[e,:]
    biasq_kernel<<<6144, 256>>>(p_b2, in_proj_w, p_bqk);

    // qkv = bef @ Wcomb^T + biasq[batch]   (exact fp32; v1 eliminated)
    gemm128<2><<<dim3(12, 49), 256>>>(bef, p_wc, p_qkv, p_bqk, 512, 512, 512, 1536, 1536);

    size_t attn_smem = (2 * 196 * 65 + 8 * 256) * sizeof(float);
    cudaFuncSetAttribute(attn_kernel, cudaFuncAttributeMaxDynamicSharedMemorySize, (int)attn_smem);
    attn_kernel<<<256, 256, attn_smem>>>(p_qkv, aoh, aol);

    // fused weights: Wq = q_w @ conv2_w @ out_proj_w ; bq = q_b + q_w@conv2_b
    gemm64_nt<<<dim3(8, 8), 256>>>(conv2_w, out_proj_w, p_w67, 512, 512, 512, 512);
    gemm64_nt<<<dim3(8, 8), 256>>>(q_w, p_w67, p_wq, 512, 512, 512, 512);
    bq_kernel<<<64, 256>>>(q_w, conv2_b, q_b, p_bq);
    split_vec_kernel<<<256, 256>>>((const float4*)p_wq, (uint2*)wqh, (uint2*)wql, 512 * 128);

    // QL = ao @ Wq^T + bq ; KL = aft @ k_w^T + k_b   (bf16x3 mma, split out)
    mma_gemm_b1<<<dim3(4, 49), 256, MG_SMEM>>>(aoh, aol, wqh, wql, qlh, qll, p_bq);
    mma_gemm_b1<<<dim3(4, 49), 256, MG_SMEM>>>(afth, aftl, kwh, kwl, klh, kll, k_b);

    // pair GEMM + fused max epilogue (cp.async double-buffered)
    pair_mma_kernel<<<dim3(49, 49), 256, PK_SMEM>>>(qlh, qll, klh, kll, p_rp, p_cp);

    reduce_s_kernel<<<1024, 256>>>(p_rp, p_cp, logit_scale, p_S);
    loss_kernel<<<1, 1024>>>(p_S, (float*)d_out);
}

// round 13
// speedup vs baseline: 1.1237x; 1.0984x over previous
#include <cuda_runtime.h>
#include <cuda_bf16.h>
#include <math.h>
#include <stdint.h>

// Shapes fixed: B=32, LV=196, LT=40, D=512, H=8, DH=64, R=B*LV=6272 (=49*128)

// ---------------------------------------------------------------------------
// Scratch buffer layout (float slots)
// ---------------------------------------------------------------------------
#define OFF_SM    0u
#define OFF_B2    16384u
#define OFF_BQ    32768u
#define OFF_W67   33280u
#define OFF_WQ    295424u
#define OFF_S     557568u
#define OFF_RP    558592u
#define OFF_CP    759296u
#define OFF_WC    960000u    // Wcomb 1536x512 = 786432
#define OFF_BQK   1746432u   // biasq 32x1536 = 49152
#define OFF_QKV   1795584u   // 9633792 fp32
#define OFF_AOH   11429376u
#define OFF_AOL   13035008u
#define OFF_AFTH  14640640u
#define OFF_AFTL  16246272u
#define OFF_QLH   17851904u
#define OFF_QLL   19457536u
#define OFF_KLH   21063168u
#define OFF_KLL   22668800u
#define OFF_WQH   24274432u
#define OFF_WQL   24339968u
#define OFF_KWH   24405504u
#define OFF_KWL   24471040u
#define OFF_BEFH  24536576u  // bf16 6272x512 = 1605632 slots
#define OFF_BEFL  26142208u
#define OFF_WCH   27747840u  // bf16 1536x512 = 393216 slots
#define OFF_WCL   28141056u
#define TOTAL_F   28534272u

__device__ __align__(256) float g_buf[TOTAL_F];

// ---------------------------------------------------------------------------
// mma.sync / ldmatrix / cp.async helpers
// ---------------------------------------------------------------------------
__device__ __forceinline__ uint32_t smem_u32(const void* p) {
    uint32_t a;
    asm("{ .reg .u64 t; cvta.to.shared.u64 t, %1; cvt.u32.u64 %0, t; }" : "=r"(a) : "l"(p));
    return a;
}
__device__ __forceinline__ void ldsm_x4(uint32_t* r, uint32_t addr) {
    asm volatile("ldmatrix.sync.aligned.m8n8.x4.shared.b16 {%0,%1,%2,%3}, [%4];"
                 : "=r"(r[0]), "=r"(r[1]), "=r"(r[2]), "=r"(r[3]) : "r"(addr));
}
__device__ __forceinline__ void ldsm_x2(uint32_t* r, uint32_t addr) {
    asm volatile("ldmatrix.sync.aligned.m8n8.x2.shared.b16 {%0,%1}, [%2];"
                 : "=r"(r[0]), "=r"(r[1]) : "r"(addr));
}
__device__ __forceinline__ void mma_bf16(float* d, const uint32_t* a, const uint32_t* b) {
    asm volatile("mma.sync.aligned.m16n8k16.row.col.f32.bf16.bf16.f32 "
                 "{%0,%1,%2,%3}, {%4,%5,%6,%7}, {%8,%9}, {%0,%1,%2,%3};"
                 : "+f"(d[0]), "+f"(d[1]), "+f"(d[2]), "+f"(d[3])
                 : "r"(a[0]), "r"(a[1]), "r"(a[2]), "r"(a[3]), "r"(b[0]), "r"(b[1]));
}
__device__ __forceinline__ void cp_async16(uint32_t dst, const void* src) {
    asm volatile("cp.async.cg.shared.global [%0], [%1], 16;" :: "r"(dst), "l"(src) : "memory");
}
__device__ __forceinline__ void cp_commit() {
    asm volatile("cp.async.commit_group;" ::: "memory");
}
template<int N>
__device__ __forceinline__ void cp_wait() {
    asm volatile("cp.async.wait_group %0;" :: "n"(N) : "memory");
}
#define SWZ128(off) ((off) ^ (((off) >> 3) & 0x70))

__device__ __forceinline__ unsigned enc_f(float f) {
    unsigned u = __float_as_uint(f);
    return u ^ ((((int)u >> 31)) | 0x80000000u);
}
__device__ __forceinline__ float dec_f(unsigned u) {
    unsigned m = (u & 0x80000000u) ? 0x80000000u : 0xFFFFFFFFu;
    return __uint_as_float(u ^ m);
}

// ---------------------------------------------------------------------------
__global__ void sent_mean_kernel(const float* __restrict__ sentf,
                                 const float* __restrict__ masks,
                                 float* __restrict__ sm) {
    int b = blockIdx.x, d = threadIdx.x;
    float s = 0.f;
    #pragma unroll
    for (int t = 0; t < 40; t++)
        s += sentf[(b * 40 + t) * 512 + d] * masks[b * 40 + t];
    sm[b * 512 + d] = s * (1.f / 40.f);
}

__global__ void bias2_kernel(const float* __restrict__ conv1_w,
                             const float* __restrict__ conv1_b,
                             const float* __restrict__ sm,
                             float* __restrict__ b2) {
    int gw = (blockIdx.x * blockDim.x + threadIdx.x) >> 5;
    int lane = threadIdx.x & 31;
    int b = gw >> 9, o = gw & 511;
    const float* wrow = conv1_w + o * 1024 + 512;
    const float* srow = sm + b * 512;
    float s = 0.f;
    for (int c = lane; c < 512; c += 32) s += wrow[c] * srow[c];
    #pragma unroll
    for (int off = 16; off; off >>= 1) s += __shfl_xor_sync(0xffffffffu, s, off);
    if (lane == 0) b2[b * 512 + o] = conv1_b[o] + s;
}

// biasq[b][e] = sum_k b2[b,k] * in_proj[e,k]   (warp per output, 32x1536)
__global__ void biasq_kernel(const float* __restrict__ b2,
                             const float* __restrict__ in_proj,
                             float* __restrict__ biasq) {
    int gw = blockIdx.x * 8 + (threadIdx.x >> 5);
    int lane = threadIdx.x & 31;
    int b = gw / 1536, e = gw % 1536;
    const float* brow = b2 + b * 512;
    const float* wrow = in_proj + e * 512;
    float s = 0.f;
    for (int c = lane; c < 512; c += 32) s += brow[c] * wrow[c];
    #pragma unroll
    for (int off = 16; off; off >>= 1) s += __shfl_xor_sync(0xffffffffu, s, off);
    if (lane == 0) biasq[gw] = s;
}

// warp-per-output: bq[q] = q_b[q] + sum_o q_w[q,o]*conv2_b[o]
__global__ void bq_kernel(const float* __restrict__ q_w,
                          const float* __restrict__ conv2_b,
                          const float* __restrict__ q_b,
                          float* __restrict__ bq) {
    int gw = blockIdx.x * 8 + (threadIdx.x >> 5);
    int lane = threadIdx.x & 31;
    const float* row = q_w + gw * 512;
    float s = 0.f;
    for (int c = lane; c < 512; c += 32) s += row[c] * conv2_b[c];
    #pragma unroll
    for (int off = 16; off; off >>= 1) s += __shfl_xor_sync(0xffffffffu, s, off);
    if (lane == 0) bq[gw] = q_b[gw] + s;
}

// ---------------------------------------------------------------------------
// Small fp32 GEMM for weight fusions. C = A(MxK)*B(KxN) (both row-major).
// ---------------------------------------------------------------------------
__global__ void gemm64_nt(const float* __restrict__ A, const float* __restrict__ B,
                          float* __restrict__ C, int K, int lda, int ldb, int ldc) {
    __shared__ float As[32][65];
    __shared__ float Bs[32][65];
    int tid = threadIdx.x;
    int tx = tid & 15, ty = tid >> 4;
    int n0 = blockIdx.x * 64, m0 = blockIdx.y * 64;
    float acc[4][4] = {};
    for (int k0 = 0; k0 < K; k0 += 32) {
        #pragma unroll
        for (int i = 0; i < 8; i++) {
            int idx = tid + i * 256;
            int k = idx & 31, r = idx >> 5;
            As[k][r] = A[(m0 + r) * lda + k0 + k];
            int n = idx & 63, kk = idx >> 6;
            Bs[kk][n] = B[(k0 + kk) * ldb + n0 + n];
        }
        __syncthreads();
        #pragma unroll
        for (int k = 0; k < 32; k++) {
            float ar[4], br[4];
            #pragma unroll
            for (int i = 0; i < 4; i++) ar[i] = As[k][ty * 4 + i];
            #pragma unroll
            for (int j = 0; j < 4; j++) br[j] = Bs[k][tx * 4 + j];
            #pragma unroll
            for (int i = 0; i < 4; i++)
                #pragma unroll
                for (int j = 0; j < 4; j++) acc[i][j] += ar[i] * br[j];
        }
        __syncthreads();
    }
    #pragma unroll
    for (int i = 0; i < 4; i++)
        #pragma unroll
        for (int j = 0; j < 4; j++)
            C[(m0 + ty * 4 + i) * ldc + n0 + tx * 4 + j] = acc[i][j];
}

// ---------------------------------------------------------------------------
// Vectorized split: hi = bf16(x), lo = bf16(x - hi). Contiguous, n % 4 == 0.
// ---------------------------------------------------------------------------
__global__ void split_vec_kernel(const float4* __restrict__ src,
                                 uint2* __restrict__ hi,
                                 uint2* __restrict__ lo, int n4) {
    for (int i = blockIdx.x * blockDim.x + threadIdx.x; i < n4; i += gridDim.x * blockDim.x) {
        float4 x = src[i];
        __nv_bfloat162 h0, h1, l0, l1;
        h0.x = __float2bfloat16(x.x); h0.y = __float2bfloat16(x.y);
        h1.x = __float2bfloat16(x.z); h1.y = __float2bfloat16(x.w);
        l0.x = __float2bfloat16(x.x - __bfloat162float(h0.x));
        l0.y = __float2bfloat16(x.y - __bfloat162float(h0.y));
        l1.x = __float2bfloat16(x.z - __bfloat162float(h1.x));
        l1.y = __float2bfloat16(x.w - __bfloat162float(h1.y));
        hi[i] = make_uint2(*(uint32_t*)&h0, *(uint32_t*)&h1);
        lo[i] = make_uint2(*(uint32_t*)&l0, *(uint32_t*)&l1);
    }
}

__global__ void init_parts_kernel(unsigned* __restrict__ p, int n) {
    for (int i = blockIdx.x * blockDim.x + threadIdx.x; i < n; i += gridDim.x * blockDim.x)
        p[i] = 0x007FFFFFu;   // enc(-inf)
}

// ---------------------------------------------------------------------------
// bf16x3 mma GEMM: C[M,N] = A(Mx512)@W(Nx512)^T + bias, K=512.
// MODE 1: bf16 split out (ld 512), + bias[n].
// MODE 2: fp32 out (ldc), + bias[(r/196)*biasld + n].
// 128x128 CTA tile, 8 warps x (64x32).
// ---------------------------------------------------------------------------
#define MG_SMEM 65536
#define SM_AH 0
#define SM_AL 16384
#define SM_BH 32768
#define SM_BL 49152

template<int MODE>
__global__ void __launch_bounds__(256) mma_gemm(
        const __nv_bfloat16* __restrict__ Ah, const __nv_bfloat16* __restrict__ Al,
        const __nv_bfloat16* __restrict__ Wh, const __nv_bfloat16* __restrict__ Wl,
        __nv_bfloat16* __restrict__ outh, __nv_bfloat16* __restrict__ outl,
        float* __restrict__ outf, const float* __restrict__ bias,
        int ldc, int biasld) {
    extern __shared__ char smem[];
    int tid = threadIdx.x;
    int wid = tid >> 5, lane = tid & 31;
    int m0 = blockIdx.y * 128, n0 = blockIdx.x * 128;
    int wm0 = (wid >> 2) * 64, wn0 = (wid & 3) * 32;

    int a_row = wm0 + (lane & 15);
    int a_ch  = (lane >> 4);
    int b_row = wn0 + (lane & 7);
    int b_ch  = ((lane >> 3) & 1);
    uint32_t smem_b = smem_u32(smem);

    float d[4][4][4];
    #pragma unroll
    for (int i = 0; i < 4; i++)
        #pragma unroll
        for (int j = 0; j < 4; j++)
            #pragma unroll
            for (int q = 0; q < 4; q++) d[i][j][q] = 0.f;

    for (int kc = 0; kc < 8; kc++) {
        __syncthreads();
        #pragma unroll
        for (int t = 0; t < 4; t++) {
            int s2 = tid + t * 256;
            int row = s2 >> 3, sc = s2 & 7;
            uint32_t sw = SWZ128((uint32_t)(row * 128 + sc * 16));
            long ga = (long)(m0 + row) * 512 + kc * 64 + sc * 8;
            long gb = (long)(n0 + row) * 512 + kc * 64 + sc * 8;
            *(uint4*)(smem + SM_AH + sw) = *(const uint4*)(Ah + ga);
            *(uint4*)(smem + SM_AL + sw) = *(const uint4*)(Al + ga);
            *(uint4*)(smem + SM_BH + sw) = *(const uint4*)(Wh + gb);
            *(uint4*)(smem + SM_BL + sw) = *(const uint4*)(Wl + gb);
        }
        __syncthreads();

        #pragma unroll
        for (int ks = 0; ks < 4; ks++) {
            int ach = (ks * 2 + a_ch) ^ (a_row & 7);
            int bch = (ks * 2 + b_ch) ^ (b_row & 7);
            uint32_t ah[4][4], bh[4][2], bl[4][2], al[4][4];
            #pragma unroll
            for (int i = 0; i < 4; i++)
                ldsm_x4(ah[i], smem_b + SM_AH + (a_row + i * 16) * 128 + ach * 16);
            #pragma unroll
            for (int j = 0; j < 4; j++)
                ldsm_x2(bh[j], smem_b + SM_BH + (b_row + j * 8) * 128 + bch * 16);
            #pragma unroll
            for (int i = 0; i < 4; i++)
                #pragma unroll
                for (int j = 0; j < 4; j++) mma_bf16(d[i][j], ah[i], bh[j]);
            #pragma unroll
            for (int j = 0; j < 4; j++)
                ldsm_x2(bl[j], smem_b + SM_BL + (b_row + j * 8) * 128 + bch * 16);
            #pragma unroll
            for (int i = 0; i < 4; i++)
                #pragma unroll
                for (int j = 0; j < 4; j++) mma_bf16(d[i][j], ah[i], bl[j]);
            #pragma unroll
            for (int i = 0; i < 4; i++)
                ldsm_x4(al[i], smem_b + SM_AL + (a_row + i * 16) * 128 + ach * 16);
            #pragma unroll
            for (int i = 0; i < 4; i++)
                #pragma unroll
                for (int j = 0; j < 4; j++) mma_bf16(d[i][j], al[i], bh[j]);
        }
    }

    int fr = lane >> 2, fc = (lane & 3) * 2;
    #pragma unroll
    for (int i = 0; i < 4; i++) {
        #pragma unroll
        for (int j = 0; j < 4; j++) {
            int gc = n0 + wn0 + j * 8 + fc;
            #pragma unroll
            for (int hh = 0; hh < 2; hh++) {
                int gr = m0 + wm0 + i * 16 + fr + hh * 8;
                float v0 = d[i][j][hh * 2 + 0];
                float v1 = d[i][j][hh * 2 + 1];
                if (MODE == 1) {
                    v0 += bias[gc]; v1 += bias[gc + 1];
                    __nv_bfloat162 hp, lp;
                    hp.x = __float2bfloat16(v0);
                    hp.y = __float2bfloat16(v1);
                    lp.x = __float2bfloat16(v0 - __bfloat162float(hp.x));
                    lp.y = __float2bfloat16(v1 - __bfloat162float(hp.y));
                    *(uint32_t*)&outh[(long)gr * 512 + gc] = *(uint32_t*)&hp;
                    *(uint32_t*)&outl[(long)gr * 512 + gc] = *(uint32_t*)&lp;
                } else {
                    int boff = (gr / 196) * biasld;
                    v0 += bias[boff + gc]; v1 += bias[boff + gc + 1];
                    *(float2*)&outf[(long)gr * ldc + gc] = make_float2(v0, v1);
                }
            }
        }
    }
}

// ---------------------------------------------------------------------------
// Attention: one CTA per (b,h). 4 query rows per warp iteration, d-outer QK.
// ---------------------------------------------------------------------------
__global__ void attn_kernel(const float* __restrict__ qkv,
                            __nv_bfloat16* __restrict__ outh,
                            __nv_bfloat16* __restrict__ outl) {
    int b = blockIdx.x >> 3, h = blockIdx.x & 7;
    extern __shared__ float smemf[];
    float* ks = smemf;                    // 196*65
    float* vs = smemf + 196 * 65;         // 196*65
    float* qs = smemf + 2 * 196 * 65;     // 8*256
    int tid = threadIdx.x;
    const float* base = qkv + b * (196 * 1536) + h * 64;
    for (int idx = tid; idx < 196 * 64; idx += 256) {
        int m = idx >> 6, d = idx & 63;
        ks[m * 65 + d] = base[m * 1536 + 512 + d];
        vs[m * 65 + d] = base[m * 1536 + 1024 + d];
    }
    __syncthreads();
    int w = tid >> 5, lane = tid & 31;
    float* q0 = qs + w * 256;

    for (int l0 = w; l0 < 196; l0 += 32) {
        bool has[4];
        #pragma unroll
        for (int rr = 0; rr < 4; rr++) {
            int lr = l0 + rr * 8;
            has[rr] = lr < 196;
            if (has[rr]) {
                q0[rr * 64 + lane]      = base[lr * 1536 + lane];
                q0[rr * 64 + lane + 32] = base[lr * 1536 + lane + 32];
            } else {
                q0[rr * 64 + lane]      = 0.f;
                q0[rr * 64 + lane + 32] = 0.f;
            }
        }
        __syncwarp();

        float s[4][7];
        #pragma unroll
        for (int rr = 0; rr < 4; rr++)
            #pragma unroll
            for (int j = 0; j < 7; j++) s[rr][j] = 0.f;

        for (int d = 0; d < 64; d++) {
            float kv[7];
            #pragma unroll
            for (int j = 0; j < 6; j++) kv[j] = ks[(j * 32 + lane) * 65 + d];
            kv[6] = (lane < 4) ? ks[(192 + lane) * 65 + d] : 0.f;
            #pragma unroll
            for (int rr = 0; rr < 4; rr++) {
                float qv = q0[rr * 64 + d];
                #pragma unroll
                for (int j = 0; j < 7; j++) s[rr][j] += qv * kv[j];
            }
        }
        #pragma unroll
        for (int rr = 0; rr < 4; rr++) {
            #pragma unroll
            for (int j = 0; j < 7; j++) s[rr][j] *= 0.125f;
            if (lane >= 4) s[rr][6] = -INFINITY;
        }

        float inv[4];
        #pragma unroll
        for (int rr = 0; rr < 4; rr++) {
            float mx = s[rr][0];
            #pragma unroll
            for (int j = 1; j < 7; j++) mx = fmaxf(mx, s[rr][j]);
            #pragma unroll
            for (int off = 16; off; off >>= 1)
                mx = fmaxf(mx, __shfl_xor_sync(0xffffffffu, mx, off));
            float sum = 0.f;
            #pragma unroll
            for (int j = 0; j < 7; j++) { s[rr][j] = expf(s[rr][j] - mx); sum += s[rr][j]; }
            #pragma unroll
            for (int off = 16; off; off >>= 1)
                sum += __shfl_xor_sync(0xffffffffu, sum, off);
            inv[rr] = 1.f / sum;
        }

        float o0[4] = {0.f, 0.f, 0.f, 0.f};
        float o1[4] = {0.f, 0.f, 0.f, 0.f};
        #pragma unroll
        for (int j = 0; j < 7; j++) {
            #pragma unroll
            for (int mm = 0; mm < 32; mm++) {
                int m = j * 32 + mm;
                if (m >= 196) break;
                float v0 = vs[m * 65 + lane];
                float v1 = vs[m * 65 + lane + 32];
                #pragma unroll
                for (int rr = 0; rr < 4; rr++) {
                    float p = __shfl_sync(0xffffffffu, s[rr][j], mm);
                    o0[rr] += p * v0;
                    o1[rr] += p * v1;
                }
            }
        }
        #pragma unroll
        for (int rr = 0; rr < 4; rr++) {
            if (!has[rr]) continue;
            int r = b * 196 + l0 + rr * 8;
            float x0 = o0[rr] * inv[rr], x1 = o1[rr] * inv[rr];
            long i0 = (long)r * 512 + h * 64 + lane;
            __nv_bfloat16 h0 = __float2bfloat16(x0);
            __nv_bfloat16 h1 = __float2bfloat16(x1);
            outh[i0]      = h0;
            outh[i0 + 32] = h1;
            outl[i0]      = __float2bfloat16(x0 - __bfloat162float(h0));
            outl[i0 + 32] = __float2bfloat16(x1 - __bfloat162float(h1));
        }
        __syncwarp();
    }
}

// ---------------------------------------------------------------------------
// Pair kernel via mma.sync bf16x3 with fused row/col max epilogue.
// 2-stage cp.async pipeline (2 x 64KB smem buffers).
// ---------------------------------------------------------------------------
#define PK_SMEM 131072
#define PK_BUF  65536

__global__ void __launch_bounds__(256) pair_mma_kernel(
        const __nv_bfloat16* __restrict__ QLh, const __nv_bfloat16* __restrict__ QLl,
        const __nv_bfloat16* __restrict__ KLh, const __nv_bfloat16* __restrict__ KLl,
        unsigned* __restrict__ rowparts, unsigned* __restrict__ colparts) {
    extern __shared__ char smem[];
    float (*Ct)[130] = (float(*)[130])smem;
    int tid = threadIdx.x;
    int wid = tid >> 5, lane = tid & 31;
    int m0 = blockIdx.y * 128, n0 = blockIdx.x * 128;
    int wm0 = (wid >> 2) * 64, wn0 = (wid & 3) * 32;

    int a_row = wm0 + (lane & 15);
    int a_ch  = (lane >> 4);
    int b_row = wn0 + (lane & 7);
    int b_ch  = ((lane >> 3) & 1);
    uint32_t smem_b = smem_u32(smem);

    float d[4][4][4];
    #pragma unroll
    for (int i = 0; i < 4; i++)
        #pragma unroll
        for (int j = 0; j < 4; j++)
            #pragma unroll
            for (int q = 0; q < 4; q++) d[i][j][q] = 0.f;

    auto stage = [&](int kc, int buf) {
        uint32_t b0 = smem_b + buf * PK_BUF;
        #pragma unroll
        for (int t = 0; t < 4; t++) {
            int s2 = tid + t * 256;
            int row = s2 >> 3, sc = s2 & 7;
            uint32_t sw = SWZ128((uint32_t)(row * 128 + sc * 16));
            long ga = (long)(m0 + row) * 512 + kc * 64 + sc * 8;
            long gb = (long)(n0 + row) * 512 + kc * 64 + sc * 8;
            cp_async16(b0 + SM_AH + sw, QLh + ga);
            cp_async16(b0 + SM_AL + sw, QLl + ga);
            cp_async16(b0 + SM_BH + sw, KLh + gb);
            cp_async16(b0 + SM_BL + sw, KLl + gb);
        }
        cp_commit();
    };

    stage(0, 0);
    for (int kc = 0; kc < 8; kc++) {
        if (kc < 7) stage(kc + 1, (kc + 1) & 1);
        if (kc < 7) cp_wait<1>(); else cp_wait<0>();
        __syncthreads();
        uint32_t bofs = (uint32_t)((kc & 1) * PK_BUF);

        #pragma unroll
        for (int ks = 0; ks < 4; ks++) {
            int ach = (ks * 2 + a_ch) ^ (a_row & 7);
            int bch = (ks * 2 + b_ch) ^ (b_row & 7);
            uint32_t ah[4][4], bh[4][2], bl[4][2], al[4][4];
            #pragma unroll
            for (int i = 0; i < 4; i++)
                ldsm_x4(ah[i], smem_b + bofs + SM_AH + (a_row + i * 16) * 128 + ach * 16);
            #pragma unroll
            for (int j = 0; j < 4; j++)
                ldsm_x2(bh[j], smem_b + bofs + SM_BH + (b_row + j * 8) * 128 + bch * 16);
            #pragma unroll
            for (int i = 0; i < 4; i++)
                #pragma unroll
                for (int j = 0; j < 4; j++) mma_bf16(d[i][j], ah[i], bh[j]);
            #pragma unroll
            for (int j = 0; j < 4; j++)
                ldsm_x2(bl[j], smem_b + bofs + SM_BL + (b_row + j * 8) * 128 + bch * 16);
            #pragma unroll
            for (int i = 0; i < 4; i++)
                #pragma unroll
                for (int j = 0; j < 4; j++) mma_bf16(d[i][j], ah[i], bl[j]);
            #pragma unroll
            for (int i = 0; i < 4; i++)
                ldsm_x4(al[i], smem_b + bofs + SM_AL + (a_row + i * 16) * 128 + ach * 16);
            #pragma unroll
            for (int i = 0; i < 4; i++)
                #pragma unroll
                for (int j = 0; j < 4; j++) mma_bf16(d[i][j], al[i], bh[j]);
        }
        __syncthreads();
    }

    int fr = lane >> 2, fc = (lane & 3) * 2;
    #pragma unroll
    for (int i = 0; i < 4; i++) {
        #pragma unroll
        for (int j = 0; j < 4; j++) {
            int r = wm0 + i * 16 + fr, c = wn0 + j * 8 + fc;
            *(float2*)&Ct[r][c]     = make_float2(d[i][j][0], d[i][j][1]);
            *(float2*)&Ct[r + 8][c] = make_float2(d[i][j][2], d[i][j][3]);
        }
    }
    __syncthreads();

    if (tid < 128) {
        int r = tid, gr = m0 + r;
        int b0 = n0 / 196;
        int bnd = (b0 + 1) * 196 - n0;
        if (bnd > 128) bnd = 128;
        float m1 = -INFINITY, m2 = -INFINITY;
        for (int c = 0; c < 128; c++) {
            float v = Ct[r][c];
            if (c < bnd) m1 = fmaxf(m1, v); else m2 = fmaxf(m2, v);
        }
        atomicMax(&rowparts[b0 * 6272 + gr], enc_f(m1));
        if (bnd < 128)
            atomicMax(&rowparts[(b0 + 1) * 6272 + gr], enc_f(m2));
    } else {
        int c = tid - 128, gc = n0 + c;
        int a0 = m0 / 196;
        int bnd = (a0 + 1) * 196 - m0;
        if (bnd > 128) bnd = 128;
        float m1 = -INFINITY, m2 = -INFINITY;
        for (int r = 0; r < 128; r++) {
            float v = Ct[r][c];
            if (r < bnd) m1 = fmaxf(m1, v); else m2 = fmaxf(m2, v);
        }
        atomicMax(&colparts[a0 * 6272 + gc], enc_f(m1));
        if (bnd < 128)
            atomicMax(&colparts[(a0 + 1) * 6272 + gc], enc_f(m2));
    }
}

// ---------------------------------------------------------------------------
__global__ void reduce_s_kernel(const unsigned* __restrict__ rowparts,
                                const unsigned* __restrict__ colparts,
                                const float* __restrict__ logit_scale,
                                float* __restrict__ S) {
    int pair = blockIdx.x, tid = threadIdx.x;
    int a = pair >> 5, b = pair & 31;
    float s = 0.f;
    for (int l = tid; l < 196; l += 256)
        s += dec_f(rowparts[b * 6272 + a * 196 + l]);
    for (int m = tid; m < 196; m += 256)
        s += dec_f(colparts[a * 6272 + b * 196 + m]);
    __shared__ float red[256];
    red[tid] = s;
    __syncthreads();
    for (int st = 128; st; st >>= 1) {
        if (tid < st) red[tid] += red[tid + st];
        __syncthreads();
    }
    if (tid == 0) S[pair] = 0.5f * red[0] * (1.f / 196.f) * expf(logit_scale[0]);
}

__global__ void loss_kernel(const float* __restrict__ S, float* __restrict__ out) {
    int tid = threadIdx.x;
    int w = tid >> 5, lane = tid & 31;
    float rv = S[w * 32 + lane];
    float cv = S[lane * 32 + w];
    float rm = rv, cm = cv;
    #pragma unroll
    for (int off = 16; off; off >>= 1) {
        rm = fmaxf(rm, __shfl_xor_sync(0xffffffffu, rm, off));
        cm = fmaxf(cm, __shfl_xor_sync(0xffffffffu, cm, off));
    }
    float re = expf(rv - rm), cex = expf(cv - cm);
    #pragma unroll
    for (int off = 16; off; off >>= 1) {
        re  += __shfl_xor_sync(0xffffffffu, re, off);
        cex += __shfl_xor_sync(0xffffffffu, cex, off);
    }
    __shared__ float acc[32];
    if (lane == 0) {
        float dg = S[w * 33];
        acc[w] = (dg - (rm + logf(re))) + (dg - (cm + logf(cex)));
    }
    __syncthreads();
    if (tid == 0) {
        float t = 0.f;
        for (int i = 0; i < 32; i++) t += acc[i];
        out[0] = -0.5f * t * (1.f / 32.f);
    }
}

// ---------------------------------------------------------------------------
extern "C" void kernel_launch(void* const* d_in, const int* in_sizes, int n_in,
                              void* d_out, int out_size) {
    const float* bef        = (const float*)d_in[0];
    const float* sentf      = (const float*)d_in[1];
    const float* aft        = (const float*)d_in[2];
    const float* masks      = (const float*)d_in[3];
    const float* conv1_w    = (const float*)d_in[4];
    const float* conv1_b    = (const float*)d_in[5];
    const float* in_proj_w  = (const float*)d_in[6];
    const float* out_proj_w = (const float*)d_in[7];
    const float* conv2_w    = (const float*)d_in[8];
    const float* conv2_b    = (const float*)d_in[9];
    const float* q_w        = (const float*)d_in[10];
    const float* q_b        = (const float*)d_in[11];
    const float* k_w        = (const float*)d_in[12];
    const float* k_b        = (const float*)d_in[13];
    const float* logit_scale= (const float*)d_in[14];

    float* base = nullptr;
    cudaGetSymbolAddress((void**)&base, g_buf);
    float* p_sm  = base + OFF_SM;
    float* p_b2  = base + OFF_B2;
    float* p_bq  = base + OFF_BQ;
    float* p_w67 = base + OFF_W67;
    float* p_wq  = base + OFF_WQ;
    float* p_S   = base + OFF_S;
    float* p_wc  = base + OFF_WC;
    float* p_bqk = base + OFF_BQK;
    float* p_qkv = base + OFF_QKV;
    unsigned* p_rp = (unsigned*)(base + OFF_RP);
    unsigned* p_cp = (unsigned*)(base + OFF_CP);
    #define BF16P(off) ((__nv_bfloat16*)(base + (off)))
    __nv_bfloat16* aoh  = BF16P(OFF_AOH);  __nv_bfloat16* aol  = BF16P(OFF_AOL);
    __nv_bfloat16* afth = BF16P(OFF_AFTH); __nv_bfloat16* aftl = BF16P(OFF_AFTL);
    __nv_bfloat16* qlh  = BF16P(OFF_QLH);  __nv_bfloat16* qll  = BF16P(OFF_QLL);
    __nv_bfloat16* klh  = BF16P(OFF_KLH);  __nv_bfloat16* kll  = BF16P(OFF_KLL);
    __nv_bfloat16* wqh  = BF16P(OFF_WQH);  __nv_bfloat16* wql  = BF16P(OFF_WQL);
    __nv_bfloat16* kwh  = BF16P(OFF_KWH);  __nv_bfloat16* kwl  = BF16P(OFF_KWL);
    __nv_bfloat16* befh = BF16P(OFF_BEFH); __nv_bfloat16* befl = BF16P(OFF_BEFL);
    __nv_bfloat16* wch  = BF16P(OFF_WCH);  __nv_bfloat16* wcl  = BF16P(OFF_WCL);

    cudaFuncSetAttribute(mma_gemm<1>, cudaFuncAttributeMaxDynamicSharedMemorySize, MG_SMEM);
    cudaFuncSetAttribute(mma_gemm<2>, cudaFuncAttributeMaxDynamicSharedMemorySize, MG_SMEM);
    cudaFuncSetAttribute(pair_mma_kernel, cudaFuncAttributeMaxDynamicSharedMemorySize, PK_SMEM);

    // prep: text mean, per-batch conv1 bias, init partials, input splits
    sent_mean_kernel<<<32, 512>>>(sentf, masks, p_sm);
    bias2_kernel<<<2048, 256>>>(conv1_w, conv1_b, p_sm, p_b2);
    init_parts_kernel<<<256, 256>>>(p_rp, 2 * 200704);
    split_vec_kernel<<<512, 256>>>((const float4*)bef, (uint2*)befh, (uint2*)befl, 6272 * 128);
    split_vec_kernel<<<512, 256>>>((const float4*)aft, (uint2*)afth, (uint2*)aftl, 6272 * 128);
    split_vec_kernel<<<256, 256>>>((const float4*)k_w, (uint2*)kwh, (uint2*)kwl, 512 * 128);

    // fold conv1 into in_proj: Wcomb[e,c] = sum_k in_proj[e,k]*conv1_w[k,c] (image half)
    gemm64_nt<<<dim3(8, 24), 256>>>(in_proj_w, conv1_w, p_wc, 512, 512, 1024, 512);
    split_vec_kernel<<<256, 256>>>((const float4*)p_wc, (uint2*)wch, (uint2*)wcl, 1536 * 128);
    // biasq[b,e] = b2[b,:] . in_proj[e,:]
    biasq_kernel<<<6144, 256>>>(p_b2, in_proj_w, p_bqk);

    // qkv = bef @ Wcomb^T + biasq[batch]   (bf16x3 mma, fp32 out)
    mma_gemm<2><<<dim3(12, 49), 256, MG_SMEM>>>(befh, befl, wch, wcl,
                                                nullptr, nullptr, p_qkv, p_bqk, 1536, 1536);

    size_t attn_smem = (2 * 196 * 65 + 8 * 256) * sizeof(float);
    cudaFuncSetAttribute(attn_kernel, cudaFuncAttributeMaxDynamicSharedMemorySize, (int)attn_smem);
    attn_kernel<<<256, 256, attn_smem>>>(p_qkv, aoh, aol);

    // fused weights: Wq = q_w @ conv2_w @ out_proj_w ; bq = q_b + q_w@conv2_b
    gemm64_nt<<<dim3(8, 8), 256>>>(conv2_w, out_proj_w, p_w67, 512, 512, 512, 512);
    gemm64_nt<<<dim3(8, 8), 256>>>(q_w, p_w67, p_wq, 512, 512, 512, 512);
    bq_kernel<<<64, 256>>>(q_w, conv2_b, q_b, p_bq);
    split_vec_kernel<<<256, 256>>>((const float4*)p_wq, (uint2*)wqh, (uint2*)wql, 512 * 128);

    // QL = ao @ Wq^T + bq ; KL = aft @ k_w^T + k_b   (bf16x3 mma, split out)
    mma_gemm<1><<<dim3(4, 49), 256, MG_SMEM>>>(aoh, aol, wqh, wql, qlh, qll, nullptr, p_bq, 0, 0);
    mma_gemm<1><<<dim3(4, 49), 256, MG_SMEM>>>(afth, aftl, kwh, kwl, klh, kll, nullptr, k_b, 0, 0);

    // pair GEMM + fused max epilogue (cp.async double-buffered)
    pair_mma_kernel<<<dim3(49, 49), 256, PK_SMEM>>>(qlh, qll, klh, kll, p_rp, p_cp);

    reduce_s_kernel<<<1024, 256>>>(p_rp, p_cp, logit_scale, p_S);
    loss_kernel<<<1, 1024>>>(p_S, (float*)d_out);
}